// round 12
// baseline (speedup 1.0000x reference)
#include <cuda_runtime.h>
#include <cuda_bf16.h>
#include <math.h>
#include <stdint.h>

#define LNUM 4
#define BB   64
#define NNODE 511
#define SS   512
#define DD   256
#define HH   8
#define HDIM 32
#define DFFN 512
#define MTOK (BB*SS)          /* 32768 */

typedef unsigned long long ull;

/* ------------------------------------------------------------------ */
/* Scratch (device globals; no allocations allowed)                    */
/* ------------------------------------------------------------------ */
__device__ float g_x  [(size_t)MTOK*DD];          /* residual stream  */
__device__ __nv_bfloat16 g_qkv_hi[(size_t)MTOK*3*DD];
__device__ __nv_bfloat16 g_qkv_lo[(size_t)MTOK*3*DD];
__device__ __nv_bfloat16 g_a_hi[(size_t)MTOK*DD]; /* activation hi    */
__device__ __nv_bfloat16 g_a_lo[(size_t)MTOK*DD]; /* activation lo    */
__device__ __nv_bfloat16 g_f_hi[(size_t)MTOK*DFFN];
__device__ __nv_bfloat16 g_f_lo[(size_t)MTOK*DFFN];
#define WTOT 2097152
__device__ __nv_bfloat16 g_w_hi[WTOT];
__device__ __nv_bfloat16 g_w_lo[WTOT];
/* per-head bias table: [b][h][q][k] bf16 (256MB) */
__device__ __nv_bfloat16 g_bias[(size_t)BB*HH*SS*SS];

/* ------------------------------------------------------------------ */
/* helpers                                                             */
/* ------------------------------------------------------------------ */
__device__ __forceinline__ uint32_t smem_u32(const void* p) {
    return (uint32_t)__cvta_generic_to_shared((void*)p);
}
__device__ __forceinline__ void split_bf16(float v, __nv_bfloat16& h, __nv_bfloat16& l) {
    h = __float2bfloat16(v);
    l = __float2bfloat16(v - __bfloat162float(h));
}
__device__ __forceinline__ uint32_t pkbf(__nv_bfloat16 a, __nv_bfloat16 b) {
    __nv_bfloat162 t; t.x = a; t.y = b;
    return *(uint32_t*)&t;
}
__device__ __forceinline__ void cp_async16(uint32_t dst, const void* src) {
    asm volatile("cp.async.cg.shared.global [%0], [%1], 16;" :: "r"(dst), "l"(src));
}
__device__ __forceinline__ void cp_commit() {
    asm volatile("cp.async.commit_group;" ::: "memory");
}
template<int N> __device__ __forceinline__ void cp_wait() {
    asm volatile("cp.async.wait_group %0;" :: "n"(N) : "memory");
}
__device__ __forceinline__ void ldsm4(uint32_t* r, uint32_t a) {
    asm volatile("ldmatrix.sync.aligned.m8n8.x4.shared.b16 {%0,%1,%2,%3}, [%4];"
                 : "=r"(r[0]), "=r"(r[1]), "=r"(r[2]), "=r"(r[3]) : "r"(a));
}
__device__ __forceinline__ void mma_bf16(float* c, const uint32_t* a,
                                         uint32_t b0, uint32_t b1) {
    asm volatile(
        "mma.sync.aligned.m16n8k16.row.col.f32.bf16.bf16.f32 "
        "{%0,%1,%2,%3}, {%4,%5,%6,%7}, {%8,%9}, {%0,%1,%2,%3};"
        : "+f"(c[0]), "+f"(c[1]), "+f"(c[2]), "+f"(c[3])
        : "r"(a[0]), "r"(a[1]), "r"(a[2]), "r"(a[3]), "r"(b0), "r"(b1));
}

/* ------------------------------------------------------------------ */
/* embed + bias table build + weight split                             */
/* ------------------------------------------------------------------ */
__global__ void embed_kernel(const int* __restrict__ cs,
                             const float* __restrict__ patch_emb,
                             const float* __restrict__ game_token) {
    int row = blockIdx.x;
    int d   = threadIdx.x;
    int b = row >> 9, s = row & 511;
    float v;
    if (s == 0) v = game_token[d];
    else        v = patch_emb[cs[b*NNODE + s - 1]*DD + d];
    g_x[(size_t)row*DD + d] = v;
}

/* bias[b][h][q][k] = (q==0||k==0) ? 0 : edge_emb[etm[b][q-1][k-1]][h] */
__global__ void gbias_kernel(const int* __restrict__ etm,
                             const float* __restrict__ ee) {
    int q = blockIdx.x, b = blockIdx.y, t = threadIdx.x;
    int k0 = 2*t, k1 = 2*t + 1;
    int t0 = 3, t1 = 3;
    if (q > 0) {
        const int* er = etm + ((size_t)b*NNODE + (q-1))*NNODE;
        if (k0 > 0) t0 = er[k0 - 1];
        t1 = er[k1 - 1];
    }
#pragma unroll
    for (int h = 0; h < HH; ++h) {
        float b0 = (t0 < 3) ? ee[t0*HH + h] : 0.f;
        float b1 = (t1 < 3) ? ee[t1*HH + h] : 0.f;
        uint32_t pv = pkbf(__float2bfloat16(b0), __float2bfloat16(b1));
        size_t off = (((size_t)(b*HH + h)*SS + q) << 9) + k0;
        *(uint32_t*)(g_bias + off) = pv;
    }
}

__global__ void wconv_kernel(const float* __restrict__ src, int n, int off) {
    int i = blockIdx.x*256 + threadIdx.x;
    if (i >= n) return;
    float x = src[i];
    __nv_bfloat16 h, l; split_bf16(x, h, l);
    g_w_hi[off + i] = h;
    g_w_lo[off + i] = l;
}

/* ------------------------------------------------------------------ */
/* layernorm: g_a_{hi,lo} = split(LN(g_x)*g + b)   (one warp per row)  */
/* ------------------------------------------------------------------ */
__global__ void ln_kernel(const float* __restrict__ gam, const float* __restrict__ bet) {
    int w = threadIdx.x >> 5, lane = threadIdx.x & 31;
    int row = blockIdx.x*8 + w;
    const float* xr = g_x + (size_t)row*DD;
    float4 v0 = *(const float4*)(xr + lane*8);
    float4 v1 = *(const float4*)(xr + lane*8 + 4);
    float s = v0.x+v0.y+v0.z+v0.w + v1.x+v1.y+v1.z+v1.w;
    float q = v0.x*v0.x+v0.y*v0.y+v0.z*v0.z+v0.w*v0.w
            + v1.x*v1.x+v1.y*v1.y+v1.z*v1.z+v1.w*v1.w;
#pragma unroll
    for (int o = 16; o; o >>= 1) {
        s += __shfl_xor_sync(0xffffffffu, s, o);
        q += __shfl_xor_sync(0xffffffffu, q, o);
    }
    float m   = s * (1.f/256.f);
    float var = q * (1.f/256.f) - m*m;
    float rs  = rsqrtf(var + 1e-5f);
    int d = lane*8;
    float4 ga = *(const float4*)(gam + d);
    float4 gb = *(const float4*)(gam + d + 4);
    float4 ba = *(const float4*)(bet + d);
    float4 bb = *(const float4*)(bet + d + 4);
    float o8[8];
    o8[0] = (v0.x-m)*rs*ga.x + ba.x;  o8[1] = (v0.y-m)*rs*ga.y + ba.y;
    o8[2] = (v0.z-m)*rs*ga.z + ba.z;  o8[3] = (v0.w-m)*rs*ga.w + ba.w;
    o8[4] = (v1.x-m)*rs*gb.x + bb.x;  o8[5] = (v1.y-m)*rs*gb.y + bb.y;
    o8[6] = (v1.z-m)*rs*gb.z + bb.z;  o8[7] = (v1.w-m)*rs*gb.w + bb.w;
    __nv_bfloat16* hh = g_a_hi + (size_t)row*DD + d;
    __nv_bfloat16* ll = g_a_lo + (size_t)row*DD + d;
#pragma unroll
    for (int p = 0; p < 4; ++p) {
        __nv_bfloat16 h0, l0, h1, l1;
        split_bf16(o8[2*p],   h0, l0);
        split_bf16(o8[2*p+1], h1, l1);
        *(uint32_t*)(hh + 2*p) = pkbf(h0, h1);
        *(uint32_t*)(ll + 2*p) = pkbf(l0, l1);
    }
}

/* ------------------------------------------------------------------ */
/* bf16 tensor-core GEMM: C[M,Nn] (+)= A[M,K] @ W[Nn,K]^T + bias       */
/* CTA tile 128x64, warp tile 64x16 -> acc 32 regs -> true 2 CTAs/SM.  */
/* ------------------------------------------------------------------ */
#define GEMM_SMEM_BYTES (2*24576)

template<int VAR, int WB>
__global__ void __launch_bounds__(256, 2)
gemm_bf(const __nv_bfloat16* __restrict__ Ahi, const __nv_bfloat16* __restrict__ Alo,
        const __nv_bfloat16* __restrict__ Whi, const __nv_bfloat16* __restrict__ Wlo,
        const float* __restrict__ bias, float* __restrict__ C,
        __nv_bfloat16* __restrict__ Ohi, __nv_bfloat16* __restrict__ Olo,
        int Nn, int K)
{
    extern __shared__ __align__(16) __nv_bfloat16 smb[];
    const int t    = threadIdx.x;
    const int lane = t & 31;
    const int wid  = t >> 5;
    const int wm   = wid & 1;           /* 64-row half          */
    const int wn   = wid >> 1;          /* 16-col quarter       */
    const int m0   = blockIdx.y * 128;
    const int n0   = blockIdx.x * 64;
    const int NC   = K >> 5;
    const uint32_t sb = smem_u32(smb);

    const __nv_bfloat16* Ah = Ahi + (size_t)m0*K;
    const __nv_bfloat16* Al = Alo + (size_t)m0*K;
    const __nv_bfloat16* Bh = Whi + (size_t)n0*K;
    const __nv_bfloat16* Bl = Wlo + (size_t)n0*K;

    float acc[4][2][4];
#pragma unroll
    for (int i = 0; i < 4; ++i)
#pragma unroll
        for (int j = 0; j < 2; ++j)
#pragma unroll
            for (int q = 0; q < 4; ++q) acc[i][j][q] = 0.f;

    /* stage one 32-K chunk: 6 x 16B per thread */
#define GSTAGE(kc, dbase)                                                     \
    {                                                                         \
        _Pragma("unroll")                                                     \
        for (int i = 0; i < 6; ++i) {                                         \
            int id = i*256 + t;                                               \
            const __nv_bfloat16* src;                                         \
            uint32_t dst;                                                     \
            if (id < 1024) {                                                  \
                int plane = id >> 9;                                          \
                int rem = id & 511;                                           \
                int r = rem >> 2, seg = rem & 3;                              \
                src = (plane ? Al : Ah) + (size_t)r*K + (kc) + seg*8;         \
                dst = (dbase) + plane*8192 + r*64 + ((seg ^ ((r>>1)&3))<<4);  \
            } else {                                                          \
                int rem = id - 1024;                                          \
                int plane = rem >> 8;                                         \
                int rr = rem & 255;                                           \
                int r = rr >> 2, seg = rr & 3;                                \
                src = (plane ? Bl : Bh) + (size_t)r*K + (kc) + seg*8;         \
                dst = (dbase) + 16384 + plane*4096 + r*64                     \
                      + ((seg ^ ((r>>1)&3))<<4);                              \
            }                                                                 \
            cp_async16(dst, src);                                             \
        }                                                                     \
        cp_commit();                                                          \
    }

    GSTAGE(0, sb);

    const int lr = lane & 15;
    const int lc = lane >> 4;

    for (int c = 0; c < NC; ++c) {
        if (c + 1 < NC) {
            GSTAGE((c+1) << 5, sb + ((c+1)&1)*24576);
            cp_wait<1>();
        } else {
            cp_wait<0>();
        }
        __syncthreads();

        uint32_t bb = sb + (c&1)*24576;
#pragma unroll
        for (int ks = 0; ks < 2; ++ks) {
            int cseg = ks*2 + lc;
            uint32_t bh4[4], bl4[4];
            {
                int r = wn*16 + lr;
                uint32_t off = 16384 + r*64 + ((cseg ^ ((r>>1)&3))<<4);
                ldsm4(bh4, bb + off);
                ldsm4(bl4, bb + 4096 + off);
            }
#pragma unroll
            for (int mt = 0; mt < 4; ++mt) {
                int r = wm*64 + mt*16 + lr;
                uint32_t off = r*64 + ((cseg ^ ((r>>1)&3))<<4);
                uint32_t ah[4], al[4];
                ldsm4(ah, bb + off);
                ldsm4(al, bb + 8192 + off);
#pragma unroll
                for (int nt = 0; nt < 2; ++nt) {
                    mma_bf16(acc[mt][nt], ah, bh4[nt], bh4[nt+2]);
                    mma_bf16(acc[mt][nt], ah, bl4[nt], bl4[nt+2]);
                    mma_bf16(acc[mt][nt], al, bh4[nt], bh4[nt+2]);
                }
            }
        }
        __syncthreads();
    }
#undef GSTAGE

#pragma unroll
    for (int mt = 0; mt < 4; ++mt) {
#pragma unroll
        for (int nt = 0; nt < 2; ++nt) {
            int r0 = m0 + wm*64 + mt*16 + (lane >> 2);
            int cc = n0 + wn*16 + nt*8 + ((lane & 3) << 1);
            float b0 = bias[cc], b1 = bias[cc + 1];
            float v0 = acc[mt][nt][0] + b0;
            float v1 = acc[mt][nt][1] + b1;
            float v2 = acc[mt][nt][2] + b0;
            float v3 = acc[mt][nt][3] + b1;
            if (VAR == 1) {
                v0 = fmaxf(v0, 0.f); v1 = fmaxf(v1, 0.f);
                v2 = fmaxf(v2, 0.f); v3 = fmaxf(v3, 0.f);
            }
            if (WB) {
                __nv_bfloat16 h0,l0,h1,l1;
                split_bf16(v0, h0, l0); split_bf16(v1, h1, l1);
                *(uint32_t*)(Ohi + (size_t)r0*Nn + cc) = pkbf(h0, h1);
                *(uint32_t*)(Olo + (size_t)r0*Nn + cc) = pkbf(l0, l1);
                split_bf16(v2, h0, l0); split_bf16(v3, h1, l1);
                *(uint32_t*)(Ohi + (size_t)(r0+8)*Nn + cc) = pkbf(h0, h1);
                *(uint32_t*)(Olo + (size_t)(r0+8)*Nn + cc) = pkbf(l0, l1);
            } else {
                float* p0 = C + (size_t)r0*Nn + cc;
                float* p1 = C + (size_t)(r0 + 8)*Nn + cc;
                if (VAR == 2) {
                    float2 o0 = *(float2*)p0, o1 = *(float2*)p1;
                    v0 += o0.x; v1 += o0.y; v2 += o1.x; v3 += o1.y;
                }
                *(float2*)p0 = make_float2(v0, v1);
                *(float2*)p1 = make_float2(v2, v3);
            }
        }
    }
}

/* ------------------------------------------------------------------ */
/* MMA flash attention: one block per (b,h), 256 thr, 64 q-rows/warp.  */
/* QKV arrives pre-split bf16 hi/lo: Q/K staged via cp.async,          */
/* V transposed from bf16 (no cvt). Mainloop identical to r10.         */
/* ------------------------------------------------------------------ */
#define AQH 0
#define AQL 32768
#define AKH 65536
#define AKL 98304
#define AVH 131072
#define AVL 163840
#define ATT_SMEM 196608

__global__ void __launch_bounds__(256)
attn_mma() {
    extern __shared__ __align__(16) char smc[];
    const uint32_t sb = smem_u32(smc);
    const int bh = blockIdx.x;
    const int b = bh >> 3, h = bh & 7;
    const int t = threadIdx.x;
    const int w = t >> 5, lane = t & 31;

    const __nv_bfloat16* bhq = g_qkv_hi + ((size_t)b*SS)*768 + h*HDIM;
    const __nv_bfloat16* blq = g_qkv_lo + ((size_t)b*SS)*768 + h*HDIM;

    /* Q/K: pure cp.async into swizzled [row][32] layout (64B rows) */
    for (int i = t; i < 2048; i += 256) {
        int s = i >> 2, seg = i & 3;
        uint32_t qk = s*64 + (((seg) ^ (s&3))<<4);
        const size_t ro = (size_t)s*768 + seg*8;
        cp_async16(sb + AQH + qk, bhq + ro);
        cp_async16(sb + AQL + qk, blq + ro);
        cp_async16(sb + AKH + qk, bhq + ro + 256);
        cp_async16(sb + AKL + qk, blq + ro + 256);
    }
    cp_commit();
    /* V: transpose from bf16 (8 dims per uint4) */
    for (int i = t; i < 2048; i += 256) {
        int s = i >> 2, dg = (i & 3) * 8;
        uint4 vh = *(const uint4*)(bhq + (size_t)s*768 + 512 + dg);
        uint4 vl = *(const uint4*)(blq + (size_t)s*768 + 512 + dg);
        const __nv_bfloat16* ph = (const __nv_bfloat16*)&vh;
        const __nv_bfloat16* pl = (const __nv_bfloat16*)&vl;
        int kseg = s >> 3, sl = (s & 7)*2;
#pragma unroll
        for (int j = 0; j < 8; ++j) {
            int d = dg + j;
            int off = d*1024 + (((kseg) ^ (d&7))<<4) + sl;
            *(__nv_bfloat16*)(smc + AVH + off) = ph[j];
            *(__nv_bfloat16*)(smc + AVL + off) = pl[j];
        }
    }
    cp_wait<0>();
    __syncthreads();

    const int qw = w * 64;
    const int r1 = lane >> 2;
    const int c2 = (lane & 3) << 1;
    const float inv = 0.17677669529663687f;
    const __nv_bfloat16* gb = g_bias + ((size_t)(b*HH + h) << 18);

    float O[4][4][4];
    float mr[4][2], lr[4][2];
#pragma unroll
    for (int mt = 0; mt < 4; ++mt) {
#pragma unroll
        for (int dn = 0; dn < 4; ++dn)
#pragma unroll
            for (int q = 0; q < 4; ++q) O[mt][dn][q] = 0.f;
        mr[mt][0] = -1e30f; mr[mt][1] = -1e30f;
        lr[mt][0] = 0.f;    lr[mt][1] = 0.f;
    }

    const int tile = lane >> 3;

    for (int c = 0; c < 16; ++c) {
        float S[4][4][4];
#pragma unroll
        for (int mt = 0; mt < 4; ++mt)
#pragma unroll
            for (int nt = 0; nt < 4; ++nt)
#pragma unroll
                for (int q = 0; q < 4; ++q) S[mt][nt][q] = 0.f;

        /* ---- QK^T ---- */
#pragma unroll
        for (int ks = 0; ks < 2; ++ks) {
            uint32_t bkh[4][2], bkl[4][2];
#pragma unroll
            for (int np = 0; np < 2; ++np) {
                int nt = np*2 + (tile >> 1);
                int key = c*32 + nt*8 + (lane & 7);
                int seg = ks*2 + (tile & 1);
                uint32_t addr = sb + AKH + key*64 + ((seg ^ (key & 3))<<4);
                uint32_t r4[4];
                ldsm4(r4, addr);
                bkh[np*2][0] = r4[0]; bkh[np*2][1] = r4[1];
                bkh[np*2+1][0] = r4[2]; bkh[np*2+1][1] = r4[3];
                ldsm4(r4, addr + 32768);
                bkl[np*2][0] = r4[0]; bkl[np*2][1] = r4[1];
                bkl[np*2+1][0] = r4[2]; bkl[np*2+1][1] = r4[3];
            }
#pragma unroll
            for (int mt = 0; mt < 4; ++mt) {
                int rr = (tile & 1)*8 + (lane & 7);
                int row = qw + mt*16 + rr;
                int seg = ks*2 + (tile >> 1);
                uint32_t addr = sb + AQH + row*64 + ((seg ^ (row & 3))<<4);
                uint32_t aqh[4], aql[4];
                ldsm4(aqh, addr);
                ldsm4(aql, addr + 32768);
#pragma unroll
                for (int nt = 0; nt < 4; ++nt) {
                    mma_bf16(S[mt][nt], aqh, bkh[nt][0], bkh[nt][1]);
                    mma_bf16(S[mt][nt], aqh, bkl[nt][0], bkl[nt][1]);
                    mma_bf16(S[mt][nt], aql, bkh[nt][0], bkh[nt][1]);
                }
            }
        }

        /* ---- bias + scale + online softmax update ---- */
#pragma unroll
        for (int mt = 0; mt < 4; ++mt) {
#pragma unroll
            for (int h2 = 0; h2 < 2; ++h2) {
                int row = qw + mt*16 + h2*8 + r1;
                const __nv_bfloat16* gr = gb + (((size_t)row) << 9) + c*32 + c2;
                float vmax = -1e30f;
#pragma unroll
                for (int nt = 0; nt < 4; ++nt) {
                    uint32_t bp = *(const uint32_t*)(gr + nt*8);
                    __nv_bfloat162 b2 = *(__nv_bfloat162*)&bp;
                    float v0 = S[mt][nt][h2*2]   * inv + __bfloat162float(b2.x);
                    float v1 = S[mt][nt][h2*2+1] * inv + __bfloat162float(b2.y);
                    S[mt][nt][h2*2] = v0; S[mt][nt][h2*2+1] = v1;
                    vmax = fmaxf(vmax, fmaxf(v0, v1));
                }
                vmax = fmaxf(vmax, __shfl_xor_sync(0xffffffffu, vmax, 1));
                vmax = fmaxf(vmax, __shfl_xor_sync(0xffffffffu, vmax, 2));
                float mo = mr[mt][h2];
                float mn = fmaxf(mo, vmax);
                float alpha = __expf(mo - mn);
                mr[mt][h2] = mn;
                float rs = 0.f;
#pragma unroll
                for (int nt = 0; nt < 4; ++nt) {
                    float p0 = __expf(S[mt][nt][h2*2]   - mn);
                    float p1 = __expf(S[mt][nt][h2*2+1] - mn);
                    S[mt][nt][h2*2] = p0; S[mt][nt][h2*2+1] = p1;
                    rs += p0 + p1;
                }
                rs += __shfl_xor_sync(0xffffffffu, rs, 1);
                rs += __shfl_xor_sync(0xffffffffu, rs, 2);
                lr[mt][h2] = lr[mt][h2]*alpha + rs;
#pragma unroll
                for (int dn = 0; dn < 4; ++dn) {
                    O[mt][dn][h2*2]   *= alpha;
                    O[mt][dn][h2*2+1] *= alpha;
                }
            }
        }

        /* ---- PV ---- */
#pragma unroll
        for (int j = 0; j < 2; ++j) {
            uint32_t bvh[4][2], bvl[4][2];
#pragma unroll
            for (int dp = 0; dp < 2; ++dp) {
                int dn = dp*2 + (tile >> 1);
                int dim = dn*8 + (lane & 7);
                int kseg = c*4 + j*2 + (tile & 1);
                uint32_t addr = sb + AVH + dim*1024 + ((kseg ^ (dim & 7))<<4);
                uint32_t r4[4];
                ldsm4(r4, addr);
                bvh[dp*2][0] = r4[0]; bvh[dp*2][1] = r4[1];
                bvh[dp*2+1][0] = r4[2]; bvh[dp*2+1][1] = r4[3];
                ldsm4(r4, addr + 32768);
                bvl[dp*2][0] = r4[0]; bvl[dp*2][1] = r4[1];
                bvl[dp*2+1][0] = r4[2]; bvl[dp*2+1][1] = r4[3];
            }
#pragma unroll
            for (int mt = 0; mt < 4; ++mt) {
                uint32_t ph[4], pl[4];
                float p00 = S[mt][2*j][0],   p01 = S[mt][2*j][1];
                float p02 = S[mt][2*j][2],   p03 = S[mt][2*j][3];
                float p10 = S[mt][2*j+1][0], p11 = S[mt][2*j+1][1];
                float p12 = S[mt][2*j+1][2], p13 = S[mt][2*j+1][3];
                __nv_bfloat16 h00 = __float2bfloat16(p00), h01 = __float2bfloat16(p01);
                __nv_bfloat16 h02 = __float2bfloat16(p02), h03 = __float2bfloat16(p03);
                __nv_bfloat16 h10 = __float2bfloat16(p10), h11 = __float2bfloat16(p11);
                __nv_bfloat16 h12 = __float2bfloat16(p12), h13 = __float2bfloat16(p13);
                ph[0] = pkbf(h00, h01); ph[1] = pkbf(h02, h03);
                ph[2] = pkbf(h10, h11); ph[3] = pkbf(h12, h13);
                pl[0] = pkbf(__float2bfloat16(p00 - __bfloat162float(h00)),
                             __float2bfloat16(p01 - __bfloat162float(h01)));
                pl[1] = pkbf(__float2bfloat16(p02 - __bfloat162float(h02)),
                             __float2bfloat16(p03 - __bfloat162float(h03)));
                pl[2] = pkbf(__float2bfloat16(p10 - __bfloat162float(h10)),
                             __float2bfloat16(p11 - __bfloat162float(h11)));
                pl[3] = pkbf(__float2bfloat16(p12 - __bfloat162float(h12)),
                             __float2bfloat16(p13 - __bfloat162float(h13)));
#pragma unroll
                for (int dn = 0; dn < 4; ++dn) {
                    mma_bf16(O[mt][dn], ph, bvh[dn][0], bvh[dn][1]);
                    mma_bf16(O[mt][dn], ph, bvl[dn][0], bvl[dn][1]);
                    mma_bf16(O[mt][dn], pl, bvh[dn][0], bvh[dn][1]);
                }
            }
        }
    }

    /* ---- finalize: O /= l, write bf16 hi/lo ---- */
#pragma unroll
    for (int mt = 0; mt < 4; ++mt) {
#pragma unroll
        for (int h2 = 0; h2 < 2; ++h2) {
            float il = 1.f / lr[mt][h2];
            int row = b*SS + qw + mt*16 + h2*8 + r1;
#pragma unroll
            for (int dn = 0; dn < 4; ++dn) {
                float v0 = O[mt][dn][h2*2]   * il;
                float v1 = O[mt][dn][h2*2+1] * il;
                __nv_bfloat16 h0, l0, h1, l1;
                split_bf16(v0, h0, l0);
                split_bf16(v1, h1, l1);
                int col = h*HDIM + dn*8 + c2;
                *(uint32_t*)(g_a_hi + (size_t)row*DD + col) = pkbf(h0, h1);
                *(uint32_t*)(g_a_lo + (size_t)row*DD + col) = pkbf(l0, l1);
            }
        }
    }
}

/* ------------------------------------------------------------------ */
/* head                                                                */
/* ------------------------------------------------------------------ */
__global__ void head_kernel(const float* __restrict__ fc1w, const float* __restrict__ fc1b,
                            const float* __restrict__ polw, const float* __restrict__ polb,
                            const float* __restrict__ valw, const float* __restrict__ valb,
                            float* __restrict__ out) {
    __shared__ float gs[256];
    __shared__ float os[64];
    int b = blockIdx.x, t = threadIdx.x;
    const float* xr = g_x + ((size_t)b*SS)*DD;
#pragma unroll
    for (int i = 0; i < 4; ++i) gs[t + i*64] = xr[t + i*64];
    __syncthreads();
    float a = fc1b[t];
#pragma unroll 8
    for (int k = 0; k < 256; ++k) a += gs[k] * fc1w[t*256 + k];
    os[t] = fmaxf(a, 0.f);
    __syncthreads();
    if (t < 7) {
        float pacc = polb[t];
#pragma unroll
        for (int j = 0; j < 64; ++j) pacc += os[j] * polw[t*64 + j];
        out[b*7 + t] = pacc;
    }
    if (t == 7) {
        float va = valb[0];
#pragma unroll
        for (int j = 0; j < 64; ++j) va += os[j] * valw[j];
        out[BB*7 + b] = tanhf(va);
    }
}

/* ------------------------------------------------------------------ */
extern "C" void kernel_launch(void* const* d_in, const int* in_sizes, int n_in,
                              void* d_out, int out_size) {
    const int*   cs    = (const int*)d_in[0];
    const int*   etm   = (const int*)d_in[1];
    const float* pe    = (const float*)d_in[2];
    const float* gt    = (const float*)d_in[3];
    const float* ee    = (const float*)d_in[4];
    const float* in_w  = (const float*)d_in[5];
    const float* in_b  = (const float*)d_in[6];
    const float* outw  = (const float*)d_in[7];
    const float* outb  = (const float*)d_in[8];
    const float* ff1w  = (const float*)d_in[9];
    const float* ff1b  = (const float*)d_in[10];
    const float* ff2w  = (const float*)d_in[11];
    const float* ff2b  = (const float*)d_in[12];
    const float* ln1g  = (const float*)d_in[13];
    const float* ln1b  = (const float*)d_in[14];
    const float* ln2g  = (const float*)d_in[15];
    const float* ln2b  = (const float*)d_in[16];
    const float* fc1w  = (const float*)d_in[17];
    const float* fc1b  = (const float*)d_in[18];
    const float* polw  = (const float*)d_in[19];
    const float* polb  = (const float*)d_in[20];
    const float* valw  = (const float*)d_in[21];
    const float* valb  = (const float*)d_in[22];
    float* out = (float*)d_out;

    float *px;
    __nv_bfloat16 *pqh, *pql, *pah, *pal, *pfh, *pfl, *pwh, *pwl;
    cudaGetSymbolAddress((void**)&px,  g_x);
    cudaGetSymbolAddress((void**)&pqh, g_qkv_hi);
    cudaGetSymbolAddress((void**)&pql, g_qkv_lo);
    cudaGetSymbolAddress((void**)&pah, g_a_hi);
    cudaGetSymbolAddress((void**)&pal, g_a_lo);
    cudaGetSymbolAddress((void**)&pfh, g_f_hi);
    cudaGetSymbolAddress((void**)&pfl, g_f_lo);
    cudaGetSymbolAddress((void**)&pwh, g_w_hi);
    cudaGetSymbolAddress((void**)&pwl, g_w_lo);

    cudaFuncSetAttribute(attn_mma, cudaFuncAttributeMaxDynamicSharedMemorySize, ATT_SMEM);
    cudaFuncSetAttribute(gemm_bf<0,1>, cudaFuncAttributeMaxDynamicSharedMemorySize, GEMM_SMEM_BYTES);
    cudaFuncSetAttribute(gemm_bf<2,0>, cudaFuncAttributeMaxDynamicSharedMemorySize, GEMM_SMEM_BYTES);
    cudaFuncSetAttribute(gemm_bf<1,1>, cudaFuncAttributeMaxDynamicSharedMemorySize, GEMM_SMEM_BYTES);

    embed_kernel<<<MTOK, 256>>>(cs, pe, gt);
    gbias_kernel<<<dim3(512, 64), 256>>>(etm, ee);

    wconv_kernel<<<(786432 + 255)/256, 256>>>(in_w,  786432, 0);
    wconv_kernel<<<(262144 + 255)/256, 256>>>(outw,  262144, 786432);
    wconv_kernel<<<(524288 + 255)/256, 256>>>(ff1w,  524288, 1048576);
    wconv_kernel<<<(524288 + 255)/256, 256>>>(ff2w,  524288, 1572864);

    for (int i = 0; i < LNUM; ++i) {
        const int inoff  = 0       + i*196608;
        const int outoff = 786432  + i*65536;
        const int f1off  = 1048576 + i*131072;
        const int f2off  = 1572864 + i*131072;

        ln_kernel<<<MTOK/8, 256>>>(ln1g + i*DD, ln1b + i*DD);
        gemm_bf<0,1><<<dim3(12, 256), 256, GEMM_SMEM_BYTES>>>(
            pah, pal, pwh + inoff, pwl + inoff, in_b + i*768, (float*)0,
            pqh, pql, 768, 256);
        attn_mma<<<BB*HH, 256, ATT_SMEM>>>();
        gemm_bf<2,0><<<dim3(4, 256), 256, GEMM_SMEM_BYTES>>>(
            pah, pal, pwh + outoff, pwl + outoff, outb + i*256, px,
            (__nv_bfloat16*)0, (__nv_bfloat16*)0, 256, 256);
        ln_kernel<<<MTOK/8, 256>>>(ln2g + i*DD, ln2b + i*DD);
        gemm_bf<1,1><<<dim3(8, 256), 256, GEMM_SMEM_BYTES>>>(
            pah, pal, pwh + f1off, pwl + f1off, ff1b + i*512, (float*)0,
            pfh, pfl, 512, 256);
        gemm_bf<2,0><<<dim3(4, 256), 256, GEMM_SMEM_BYTES>>>(
            pfh, pfl, pwh + f2off, pwl + f2off, ff2b + i*256, px,
            (__nv_bfloat16*)0, (__nv_bfloat16*)0, 256, 512);
    }
    head_kernel<<<BB, 64>>>(fc1w, fc1b, polw, polb, valw, valb, out);
}

// round 13
// speedup vs baseline: 1.6231x; 1.6231x over previous
#include <cuda_runtime.h>
#include <cuda_bf16.h>
#include <math.h>
#include <stdint.h>

#define LNUM 4
#define BB   64
#define NNODE 511
#define SS   512
#define DD   256
#define HH   8
#define HDIM 32
#define DFFN 512
#define MTOK (BB*SS)          /* 32768 */

typedef unsigned long long ull;

/* ------------------------------------------------------------------ */
/* Scratch (device globals; no allocations allowed)                    */
/* ------------------------------------------------------------------ */
__device__ float g_x  [(size_t)MTOK*DD];          /* residual stream  */
__device__ __nv_bfloat16 g_qkv_hi[(size_t)MTOK*3*DD];
__device__ __nv_bfloat16 g_qkv_lo[(size_t)MTOK*3*DD];
__device__ __nv_bfloat16 g_a_hi[(size_t)MTOK*DD]; /* activation hi    */
__device__ __nv_bfloat16 g_a_lo[(size_t)MTOK*DD]; /* activation lo    */
__device__ __nv_bfloat16 g_f_hi[(size_t)MTOK*DFFN];
__device__ __nv_bfloat16 g_f_lo[(size_t)MTOK*DFFN];
#define WTOT 2097152
__device__ __nv_bfloat16 g_w_hi[WTOT];
__device__ __nv_bfloat16 g_w_lo[WTOT];
/* per-head bias table: [b][h][q][k] bf16 (256MB) */
__device__ __nv_bfloat16 g_bias[(size_t)BB*HH*SS*SS];

/* ------------------------------------------------------------------ */
/* helpers                                                             */
/* ------------------------------------------------------------------ */
__device__ __forceinline__ uint32_t smem_u32(const void* p) {
    return (uint32_t)__cvta_generic_to_shared((void*)p);
}
__device__ __forceinline__ void split_bf16(float v, __nv_bfloat16& h, __nv_bfloat16& l) {
    h = __float2bfloat16(v);
    l = __float2bfloat16(v - __bfloat162float(h));
}
__device__ __forceinline__ uint32_t pkbf(__nv_bfloat16 a, __nv_bfloat16 b) {
    __nv_bfloat162 t; t.x = a; t.y = b;
    return *(uint32_t*)&t;
}
__device__ __forceinline__ void cp_async16(uint32_t dst, const void* src) {
    asm volatile("cp.async.cg.shared.global [%0], [%1], 16;" :: "r"(dst), "l"(src));
}
__device__ __forceinline__ void cp_commit() {
    asm volatile("cp.async.commit_group;" ::: "memory");
}
template<int N> __device__ __forceinline__ void cp_wait() {
    asm volatile("cp.async.wait_group %0;" :: "n"(N) : "memory");
}
__device__ __forceinline__ void ldsm4(uint32_t* r, uint32_t a) {
    asm volatile("ldmatrix.sync.aligned.m8n8.x4.shared.b16 {%0,%1,%2,%3}, [%4];"
                 : "=r"(r[0]), "=r"(r[1]), "=r"(r[2]), "=r"(r[3]) : "r"(a));
}
__device__ __forceinline__ void mma_bf16(float* c, const uint32_t* a,
                                         uint32_t b0, uint32_t b1) {
    asm volatile(
        "mma.sync.aligned.m16n8k16.row.col.f32.bf16.bf16.f32 "
        "{%0,%1,%2,%3}, {%4,%5,%6,%7}, {%8,%9}, {%0,%1,%2,%3};"
        : "+f"(c[0]), "+f"(c[1]), "+f"(c[2]), "+f"(c[3])
        : "r"(a[0]), "r"(a[1]), "r"(a[2]), "r"(a[3]), "r"(b0), "r"(b1));
}

/* ------------------------------------------------------------------ */
/* embed + bias table build + weight split                             */
/* ------------------------------------------------------------------ */
__global__ void embed_kernel(const int* __restrict__ cs,
                             const float* __restrict__ patch_emb,
                             const float* __restrict__ game_token) {
    int row = blockIdx.x;
    int d   = threadIdx.x;
    int b = row >> 9, s = row & 511;
    float v;
    if (s == 0) v = game_token[d];
    else        v = patch_emb[cs[b*NNODE + s - 1]*DD + d];
    g_x[(size_t)row*DD + d] = v;
}

/* bias[b][h][q][k] = (q==0||k==0) ? 0 : edge_emb[etm[b][q-1][k-1]][h] */
__global__ void gbias_kernel(const int* __restrict__ etm,
                             const float* __restrict__ ee) {
    int q = blockIdx.x, b = blockIdx.y, t = threadIdx.x;
    int k0 = 2*t, k1 = 2*t + 1;
    int t0 = 3, t1 = 3;
    if (q > 0) {
        const int* er = etm + ((size_t)b*NNODE + (q-1))*NNODE;
        if (k0 > 0) t0 = er[k0 - 1];
        t1 = er[k1 - 1];
    }
#pragma unroll
    for (int h = 0; h < HH; ++h) {
        float b0 = (t0 < 3) ? ee[t0*HH + h] : 0.f;
        float b1 = (t1 < 3) ? ee[t1*HH + h] : 0.f;
        uint32_t pv = pkbf(__float2bfloat16(b0), __float2bfloat16(b1));
        size_t off = (((size_t)(b*HH + h)*SS + q) << 9) + k0;
        *(uint32_t*)(g_bias + off) = pv;
    }
}

__global__ void wconv_kernel(const float* __restrict__ src, int n, int off) {
    int i = blockIdx.x*256 + threadIdx.x;
    if (i >= n) return;
    float x = src[i];
    __nv_bfloat16 h, l; split_bf16(x, h, l);
    g_w_hi[off + i] = h;
    g_w_lo[off + i] = l;
}

/* ------------------------------------------------------------------ */
/* layernorm: g_a_{hi,lo} = split(LN(g_x)*g + b)   (one warp per row)  */
/* ------------------------------------------------------------------ */
__global__ void ln_kernel(const float* __restrict__ gam, const float* __restrict__ bet) {
    int w = threadIdx.x >> 5, lane = threadIdx.x & 31;
    int row = blockIdx.x*8 + w;
    const float* xr = g_x + (size_t)row*DD;
    float4 v0 = *(const float4*)(xr + lane*8);
    float4 v1 = *(const float4*)(xr + lane*8 + 4);
    float s = v0.x+v0.y+v0.z+v0.w + v1.x+v1.y+v1.z+v1.w;
    float q = v0.x*v0.x+v0.y*v0.y+v0.z*v0.z+v0.w*v0.w
            + v1.x*v1.x+v1.y*v1.y+v1.z*v1.z+v1.w*v1.w;
#pragma unroll
    for (int o = 16; o; o >>= 1) {
        s += __shfl_xor_sync(0xffffffffu, s, o);
        q += __shfl_xor_sync(0xffffffffu, q, o);
    }
    float m   = s * (1.f/256.f);
    float var = q * (1.f/256.f) - m*m;
    float rs  = rsqrtf(var + 1e-5f);
    int d = lane*8;
    float4 ga = *(const float4*)(gam + d);
    float4 gb = *(const float4*)(gam + d + 4);
    float4 ba = *(const float4*)(bet + d);
    float4 bb = *(const float4*)(bet + d + 4);
    float o8[8];
    o8[0] = (v0.x-m)*rs*ga.x + ba.x;  o8[1] = (v0.y-m)*rs*ga.y + ba.y;
    o8[2] = (v0.z-m)*rs*ga.z + ba.z;  o8[3] = (v0.w-m)*rs*ga.w + ba.w;
    o8[4] = (v1.x-m)*rs*gb.x + bb.x;  o8[5] = (v1.y-m)*rs*gb.y + bb.y;
    o8[6] = (v1.z-m)*rs*gb.z + bb.z;  o8[7] = (v1.w-m)*rs*gb.w + bb.w;
    __nv_bfloat16* hh = g_a_hi + (size_t)row*DD + d;
    __nv_bfloat16* ll = g_a_lo + (size_t)row*DD + d;
#pragma unroll
    for (int p = 0; p < 4; ++p) {
        __nv_bfloat16 h0, l0, h1, l1;
        split_bf16(o8[2*p],   h0, l0);
        split_bf16(o8[2*p+1], h1, l1);
        *(uint32_t*)(hh + 2*p) = pkbf(h0, h1);
        *(uint32_t*)(ll + 2*p) = pkbf(l0, l1);
    }
}

/* ------------------------------------------------------------------ */
/* bf16 tensor-core GEMM (r10-proven shape): CTA 128x128, warp 64x32,  */
/* K-chunk 32, cp.async double buffer, swizzled ldmatrix.              */
/* VAR: 0 plain fp32, 1 relu, 2 residual add. WB: bf16 hi/lo output.   */
/* ------------------------------------------------------------------ */
#define GEMM_SMEM_BYTES (2*32768)

template<int VAR, int WB>
__global__ void __launch_bounds__(256)
gemm_bf(const __nv_bfloat16* __restrict__ Ahi, const __nv_bfloat16* __restrict__ Alo,
        const __nv_bfloat16* __restrict__ Whi, const __nv_bfloat16* __restrict__ Wlo,
        const float* __restrict__ bias, float* __restrict__ C,
        __nv_bfloat16* __restrict__ Ohi, __nv_bfloat16* __restrict__ Olo,
        int Nn, int K)
{
    extern __shared__ __align__(16) __nv_bfloat16 smb[];
    const int t    = threadIdx.x;
    const int lane = t & 31;
    const int wid  = t >> 5;
    const int wm   = wid & 1;
    const int wn   = wid >> 1;
    const int m0   = blockIdx.y * 128;
    const int n0   = blockIdx.x * 128;
    const int NC   = K >> 5;
    const uint32_t sb = smem_u32(smb);

    const __nv_bfloat16* mp[4] = {
        Ahi + (size_t)m0*K, Alo + (size_t)m0*K,
        Whi + (size_t)n0*K, Wlo + (size_t)n0*K };

    int cid_mi[8], cid_r[8], cid_cs[8];
#pragma unroll
    for (int i = 0; i < 8; ++i) {
        int id = i*256 + t;
        cid_mi[i] = id >> 9;
        int rem = id & 511;
        cid_r[i]  = rem >> 2;
        cid_cs[i] = rem & 3;
    }

    float acc[4][4][4];
#pragma unroll
    for (int i = 0; i < 4; ++i)
#pragma unroll
        for (int j = 0; j < 4; ++j)
#pragma unroll
            for (int q = 0; q < 4; ++q) acc[i][j][q] = 0.f;

    {
        uint32_t dbase = sb;
#pragma unroll
        for (int i = 0; i < 8; ++i) {
            int r = cid_r[i], cs = cid_cs[i], mi = cid_mi[i];
            uint32_t dst = dbase + mi*8192 + r*64 + ((cs ^ ((r>>1)&3))<<4);
            cp_async16(dst, mp[mi] + (size_t)r*K + cs*8);
        }
        cp_commit();
    }

    const int lr = lane & 15;
    const int lc = lane >> 4;

    for (int c = 0; c < NC; ++c) {
        if (c + 1 < NC) {
            int kc = (c+1) << 5;
            uint32_t dbase = sb + ((c+1)&1)*32768;
#pragma unroll
            for (int i = 0; i < 8; ++i) {
                int r = cid_r[i], cs = cid_cs[i], mi = cid_mi[i];
                uint32_t dst = dbase + mi*8192 + r*64 + ((cs ^ ((r>>1)&3))<<4);
                cp_async16(dst, mp[mi] + (size_t)r*K + kc + cs*8);
            }
            cp_commit();
            cp_wait<1>();
        } else {
            cp_wait<0>();
        }
        __syncthreads();

        uint32_t bb = sb + (c&1)*32768;
#pragma unroll
        for (int ks = 0; ks < 2; ++ks) {
            int cseg = ks*2 + lc;
            uint32_t bh[2][4], bl[2][4];
#pragma unroll
            for (int np = 0; np < 2; ++np) {
                int r = wn*32 + np*16 + lr;
                uint32_t off = r*64 + ((cseg ^ ((r>>1)&3))<<4);
                ldsm4(bh[np], bb + 2*8192 + off);
                ldsm4(bl[np], bb + 3*8192 + off);
            }
#pragma unroll
            for (int mt = 0; mt < 4; ++mt) {
                int r = wm*64 + mt*16 + lr;
                uint32_t off = r*64 + ((cseg ^ ((r>>1)&3))<<4);
                uint32_t ah[4], al[4];
                ldsm4(ah, bb + off);
                ldsm4(al, bb + 8192 + off);
#pragma unroll
                for (int nt = 0; nt < 4; ++nt) {
                    int np = nt >> 1, h2 = nt & 1;
                    mma_bf16(acc[mt][nt], ah, bh[np][h2], bh[np][h2+2]);
                    mma_bf16(acc[mt][nt], ah, bl[np][h2], bl[np][h2+2]);
                    mma_bf16(acc[mt][nt], al, bh[np][h2], bh[np][h2+2]);
                }
            }
        }
        __syncthreads();
    }

#pragma unroll
    for (int mt = 0; mt < 4; ++mt) {
#pragma unroll
        for (int nt = 0; nt < 4; ++nt) {
            int r0 = m0 + wm*64 + mt*16 + (lane >> 2);
            int cc = n0 + wn*32 + nt*8 + ((lane & 3) << 1);
            float b0 = bias[cc], b1 = bias[cc + 1];
            float v0 = acc[mt][nt][0] + b0;
            float v1 = acc[mt][nt][1] + b1;
            float v2 = acc[mt][nt][2] + b0;
            float v3 = acc[mt][nt][3] + b1;
            if (VAR == 1) {
                v0 = fmaxf(v0, 0.f); v1 = fmaxf(v1, 0.f);
                v2 = fmaxf(v2, 0.f); v3 = fmaxf(v3, 0.f);
            }
            if (WB) {
                __nv_bfloat16 h0,l0,h1,l1;
                split_bf16(v0, h0, l0); split_bf16(v1, h1, l1);
                *(uint32_t*)(Ohi + (size_t)r0*Nn + cc) = pkbf(h0, h1);
                *(uint32_t*)(Olo + (size_t)r0*Nn + cc) = pkbf(l0, l1);
                split_bf16(v2, h0, l0); split_bf16(v3, h1, l1);
                *(uint32_t*)(Ohi + (size_t)(r0+8)*Nn + cc) = pkbf(h0, h1);
                *(uint32_t*)(Olo + (size_t)(r0+8)*Nn + cc) = pkbf(l0, l1);
            } else {
                float* p0 = C + (size_t)r0*Nn + cc;
                float* p1 = C + (size_t)(r0 + 8)*Nn + cc;
                if (VAR == 2) {
                    float2 o0 = *(float2*)p0, o1 = *(float2*)p1;
                    v0 += o0.x; v1 += o0.y; v2 += o1.x; v3 += o1.y;
                }
                *(float2*)p0 = make_float2(v0, v1);
                *(float2*)p1 = make_float2(v2, v3);
            }
        }
    }
}

/* ------------------------------------------------------------------ */
/* MMA flash attention: one block per (b,h), 256 thr, 64 q-rows/warp.  */
/* QKV arrives pre-split bf16 hi/lo: Q/K staged via cp.async,          */
/* V transposed from bf16 (no cvt). Mainloop = r10 (proven).           */
/* ------------------------------------------------------------------ */
#define AQH 0
#define AQL 32768
#define AKH 65536
#define AKL 98304
#define AVH 131072
#define AVL 163840
#define ATT_SMEM 196608

__global__ void __launch_bounds__(256)
attn_mma() {
    extern __shared__ __align__(16) char smc[];
    const uint32_t sb = smem_u32(smc);
    const int bh = blockIdx.x;
    const int b = bh >> 3, h = bh & 7;
    const int t = threadIdx.x;
    const int w = t >> 5, lane = t & 31;

    const __nv_bfloat16* bhq = g_qkv_hi + ((size_t)b*SS)*768 + h*HDIM;
    const __nv_bfloat16* blq = g_qkv_lo + ((size_t)b*SS)*768 + h*HDIM;

    /* Q/K: pure cp.async into swizzled [row][32] layout (64B rows) */
    for (int i = t; i < 2048; i += 256) {
        int s = i >> 2, seg = i & 3;
        uint32_t qk = s*64 + (((seg) ^ (s&3))<<4);
        const size_t ro = (size_t)s*768 + seg*8;
        cp_async16(sb + AQH + qk, bhq + ro);
        cp_async16(sb + AQL + qk, blq + ro);
        cp_async16(sb + AKH + qk, bhq + ro + 256);
        cp_async16(sb + AKL + qk, blq + ro + 256);
    }
    cp_commit();
    /* V: transpose from bf16 (8 dims per uint4) */
    for (int i = t; i < 2048; i += 256) {
        int s = i >> 2, dg = (i & 3) * 8;
        uint4 vh = *(const uint4*)(bhq + (size_t)s*768 + 512 + dg);
        uint4 vl = *(const uint4*)(blq + (size_t)s*768 + 512 + dg);
        const __nv_bfloat16* ph = (const __nv_bfloat16*)&vh;
        const __nv_bfloat16* pl = (const __nv_bfloat16*)&vl;
        int kseg = s >> 3, sl = (s & 7)*2;
#pragma unroll
        for (int j = 0; j < 8; ++j) {
            int d = dg + j;
            int off = d*1024 + (((kseg) ^ (d&7))<<4) + sl;
            *(__nv_bfloat16*)(smc + AVH + off) = ph[j];
            *(__nv_bfloat16*)(smc + AVL + off) = pl[j];
        }
    }
    cp_wait<0>();
    __syncthreads();

    const int qw = w * 64;
    const int r1 = lane >> 2;
    const int c2 = (lane & 3) << 1;
    const float inv = 0.17677669529663687f;
    const __nv_bfloat16* gb = g_bias + ((size_t)(b*HH + h) << 18);

    float O[4][4][4];
    float mr[4][2], lr[4][2];
#pragma unroll
    for (int mt = 0; mt < 4; ++mt) {
#pragma unroll
        for (int dn = 0; dn < 4; ++dn)
#pragma unroll
            for (int q = 0; q < 4; ++q) O[mt][dn][q] = 0.f;
        mr[mt][0] = -1e30f; mr[mt][1] = -1e30f;
        lr[mt][0] = 0.f;    lr[mt][1] = 0.f;
    }

    const int tile = lane >> 3;

    for (int c = 0; c < 16; ++c) {
        float S[4][4][4];
#pragma unroll
        for (int mt = 0; mt < 4; ++mt)
#pragma unroll
            for (int nt = 0; nt < 4; ++nt)
#pragma unroll
                for (int q = 0; q < 4; ++q) S[mt][nt][q] = 0.f;

        /* ---- QK^T ---- */
#pragma unroll
        for (int ks = 0; ks < 2; ++ks) {
            uint32_t bkh[4][2], bkl[4][2];
#pragma unroll
            for (int np = 0; np < 2; ++np) {
                int nt = np*2 + (tile >> 1);
                int key = c*32 + nt*8 + (lane & 7);
                int seg = ks*2 + (tile & 1);
                uint32_t addr = sb + AKH + key*64 + ((seg ^ (key & 3))<<4);
                uint32_t r4[4];
                ldsm4(r4, addr);
                bkh[np*2][0] = r4[0]; bkh[np*2][1] = r4[1];
                bkh[np*2+1][0] = r4[2]; bkh[np*2+1][1] = r4[3];
                ldsm4(r4, addr + 32768);
                bkl[np*2][0] = r4[0]; bkl[np*2][1] = r4[1];
                bkl[np*2+1][0] = r4[2]; bkl[np*2+1][1] = r4[3];
            }
#pragma unroll
            for (int mt = 0; mt < 4; ++mt) {
                int rr = (tile & 1)*8 + (lane & 7);
                int row = qw + mt*16 + rr;
                int seg = ks*2 + (tile >> 1);
                uint32_t addr = sb + AQH + row*64 + ((seg ^ (row & 3))<<4);
                uint32_t aqh[4], aql[4];
                ldsm4(aqh, addr);
                ldsm4(aql, addr + 32768);
#pragma unroll
                for (int nt = 0; nt < 4; ++nt) {
                    mma_bf16(S[mt][nt], aqh, bkh[nt][0], bkh[nt][1]);
                    mma_bf16(S[mt][nt], aqh, bkl[nt][0], bkl[nt][1]);
                    mma_bf16(S[mt][nt], aql, bkh[nt][0], bkh[nt][1]);
                }
            }
        }

        /* ---- bias + scale + online softmax update ---- */
#pragma unroll
        for (int mt = 0; mt < 4; ++mt) {
#pragma unroll
            for (int h2 = 0; h2 < 2; ++h2) {
                int row = qw + mt*16 + h2*8 + r1;
                const __nv_bfloat16* gr = gb + (((size_t)row) << 9) + c*32 + c2;
                float vmax = -1e30f;
#pragma unroll
                for (int nt = 0; nt < 4; ++nt) {
                    uint32_t bp = *(const uint32_t*)(gr + nt*8);
                    __nv_bfloat162 b2 = *(__nv_bfloat162*)&bp;
                    float v0 = S[mt][nt][h2*2]   * inv + __bfloat162float(b2.x);
                    float v1 = S[mt][nt][h2*2+1] * inv + __bfloat162float(b2.y);
                    S[mt][nt][h2*2] = v0; S[mt][nt][h2*2+1] = v1;
                    vmax = fmaxf(vmax, fmaxf(v0, v1));
                }
                vmax = fmaxf(vmax, __shfl_xor_sync(0xffffffffu, vmax, 1));
                vmax = fmaxf(vmax, __shfl_xor_sync(0xffffffffu, vmax, 2));
                float mo = mr[mt][h2];
                float mn = fmaxf(mo, vmax);
                float alpha = __expf(mo - mn);
                mr[mt][h2] = mn;
                float rs = 0.f;
#pragma unroll
                for (int nt = 0; nt < 4; ++nt) {
                    float p0 = __expf(S[mt][nt][h2*2]   - mn);
                    float p1 = __expf(S[mt][nt][h2*2+1] - mn);
                    S[mt][nt][h2*2] = p0; S[mt][nt][h2*2+1] = p1;
                    rs += p0 + p1;
                }
                rs += __shfl_xor_sync(0xffffffffu, rs, 1);
                rs += __shfl_xor_sync(0xffffffffu, rs, 2);
                lr[mt][h2] = lr[mt][h2]*alpha + rs;
#pragma unroll
                for (int dn = 0; dn < 4; ++dn) {
                    O[mt][dn][h2*2]   *= alpha;
                    O[mt][dn][h2*2+1] *= alpha;
                }
            }
        }

        /* ---- PV ---- */
#pragma unroll
        for (int j = 0; j < 2; ++j) {
            uint32_t bvh[4][2], bvl[4][2];
#pragma unroll
            for (int dp = 0; dp < 2; ++dp) {
                int dn = dp*2 + (tile >> 1);
                int dim = dn*8 + (lane & 7);
                int kseg = c*4 + j*2 + (tile & 1);
                uint32_t addr = sb + AVH + dim*1024 + ((kseg ^ (dim & 7))<<4);
                uint32_t r4[4];
                ldsm4(r4, addr);
                bvh[dp*2][0] = r4[0]; bvh[dp*2][1] = r4[1];
                bvh[dp*2+1][0] = r4[2]; bvh[dp*2+1][1] = r4[3];
                ldsm4(r4, addr + 32768);
                bvl[dp*2][0] = r4[0]; bvl[dp*2][1] = r4[1];
                bvl[dp*2+1][0] = r4[2]; bvl[dp*2+1][1] = r4[3];
            }
#pragma unroll
            for (int mt = 0; mt < 4; ++mt) {
                uint32_t ph[4], pl[4];
                float p00 = S[mt][2*j][0],   p01 = S[mt][2*j][1];
                float p02 = S[mt][2*j][2],   p03 = S[mt][2*j][3];
                float p10 = S[mt][2*j+1][0], p11 = S[mt][2*j+1][1];
                float p12 = S[mt][2*j+1][2], p13 = S[mt][2*j+1][3];
                __nv_bfloat16 h00 = __float2bfloat16(p00), h01 = __float2bfloat16(p01);
                __nv_bfloat16 h02 = __float2bfloat16(p02), h03 = __float2bfloat16(p03);
                __nv_bfloat16 h10 = __float2bfloat16(p10), h11 = __float2bfloat16(p11);
                __nv_bfloat16 h12 = __float2bfloat16(p12), h13 = __float2bfloat16(p13);
                ph[0] = pkbf(h00, h01); ph[1] = pkbf(h02, h03);
                ph[2] = pkbf(h10, h11); ph[3] = pkbf(h12, h13);
                pl[0] = pkbf(__float2bfloat16(p00 - __bfloat162float(h00)),
                             __float2bfloat16(p01 - __bfloat162float(h01)));
                pl[1] = pkbf(__float2bfloat16(p02 - __bfloat162float(h02)),
                             __float2bfloat16(p03 - __bfloat162float(h03)));
                pl[2] = pkbf(__float2bfloat16(p10 - __bfloat162float(h10)),
                             __float2bfloat16(p11 - __bfloat162float(h11)));
                pl[3] = pkbf(__float2bfloat16(p12 - __bfloat162float(h12)),
                             __float2bfloat16(p13 - __bfloat162float(h13)));
#pragma unroll
                for (int dn = 0; dn < 4; ++dn) {
                    mma_bf16(O[mt][dn], ph, bvh[dn][0], bvh[dn][1]);
                    mma_bf16(O[mt][dn], ph, bvl[dn][0], bvl[dn][1]);
                    mma_bf16(O[mt][dn], pl, bvh[dn][0], bvh[dn][1]);
                }
            }
        }
    }

    /* ---- finalize: O /= l, write bf16 hi/lo ---- */
#pragma unroll
    for (int mt = 0; mt < 4; ++mt) {
#pragma unroll
        for (int h2 = 0; h2 < 2; ++h2) {
            float il = 1.f / lr[mt][h2];
            int row = b*SS + qw + mt*16 + h2*8 + r1;
#pragma unroll
            for (int dn = 0; dn < 4; ++dn) {
                float v0 = O[mt][dn][h2*2]   * il;
                float v1 = O[mt][dn][h2*2+1] * il;
                __nv_bfloat16 h0, l0, h1, l1;
                split_bf16(v0, h0, l0);
                split_bf16(v1, h1, l1);
                int col = h*HDIM + dn*8 + c2;
                *(uint32_t*)(g_a_hi + (size_t)row*DD + col) = pkbf(h0, h1);
                *(uint32_t*)(g_a_lo + (size_t)row*DD + col) = pkbf(l0, l1);
            }
        }
    }
}

/* ------------------------------------------------------------------ */
/* head                                                                */
/* ------------------------------------------------------------------ */
__global__ void head_kernel(const float* __restrict__ fc1w, const float* __restrict__ fc1b,
                            const float* __restrict__ polw, const float* __restrict__ polb,
                            const float* __restrict__ valw, const float* __restrict__ valb,
                            float* __restrict__ out) {
    __shared__ float gs[256];
    __shared__ float os[64];
    int b = blockIdx.x, t = threadIdx.x;
    const float* xr = g_x + ((size_t)b*SS)*DD;
#pragma unroll
    for (int i = 0; i < 4; ++i) gs[t + i*64] = xr[t + i*64];
    __syncthreads();
    float a = fc1b[t];
#pragma unroll 8
    for (int k = 0; k < 256; ++k) a += gs[k] * fc1w[t*256 + k];
    os[t] = fmaxf(a, 0.f);
    __syncthreads();
    if (t < 7) {
        float pacc = polb[t];
#pragma unroll
        for (int j = 0; j < 64; ++j) pacc += os[j] * polw[t*64 + j];
        out[b*7 + t] = pacc;
    }
    if (t == 7) {
        float va = valb[0];
#pragma unroll
        for (int j = 0; j < 64; ++j) va += os[j] * valw[j];
        out[BB*7 + b] = tanhf(va);
    }
}

/* ------------------------------------------------------------------ */
extern "C" void kernel_launch(void* const* d_in, const int* in_sizes, int n_in,
                              void* d_out, int out_size) {
    const int*   cs    = (const int*)d_in[0];
    const int*   etm   = (const int*)d_in[1];
    const float* pe    = (const float*)d_in[2];
    const float* gt    = (const float*)d_in[3];
    const float* ee    = (const float*)d_in[4];
    const float* in_w  = (const float*)d_in[5];
    const float* in_b  = (const float*)d_in[6];
    const float* outw  = (const float*)d_in[7];
    const float* outb  = (const float*)d_in[8];
    const float* ff1w  = (const float*)d_in[9];
    const float* ff1b  = (const float*)d_in[10];
    const float* ff2w  = (const float*)d_in[11];
    const float* ff2b  = (const float*)d_in[12];
    const float* ln1g  = (const float*)d_in[13];
    const float* ln1b  = (const float*)d_in[14];
    const float* ln2g  = (const float*)d_in[15];
    const float* ln2b  = (const float*)d_in[16];
    const float* fc1w  = (const float*)d_in[17];
    const float* fc1b  = (const float*)d_in[18];
    const float* polw  = (const float*)d_in[19];
    const float* polb  = (const float*)d_in[20];
    const float* valw  = (const float*)d_in[21];
    const float* valb  = (const float*)d_in[22];
    float* out = (float*)d_out;

    float *px;
    __nv_bfloat16 *pqh, *pql, *pah, *pal, *pfh, *pfl, *pwh, *pwl;
    cudaGetSymbolAddress((void**)&px,  g_x);
    cudaGetSymbolAddress((void**)&pqh, g_qkv_hi);
    cudaGetSymbolAddress((void**)&pql, g_qkv_lo);
    cudaGetSymbolAddress((void**)&pah, g_a_hi);
    cudaGetSymbolAddress((void**)&pal, g_a_lo);
    cudaGetSymbolAddress((void**)&pfh, g_f_hi);
    cudaGetSymbolAddress((void**)&pfl, g_f_lo);
    cudaGetSymbolAddress((void**)&pwh, g_w_hi);
    cudaGetSymbolAddress((void**)&pwl, g_w_lo);

    cudaFuncSetAttribute(attn_mma, cudaFuncAttributeMaxDynamicSharedMemorySize, ATT_SMEM);
    cudaFuncSetAttribute(gemm_bf<0,1>, cudaFuncAttributeMaxDynamicSharedMemorySize, GEMM_SMEM_BYTES);
    cudaFuncSetAttribute(gemm_bf<2,0>, cudaFuncAttributeMaxDynamicSharedMemorySize, GEMM_SMEM_BYTES);
    cudaFuncSetAttribute(gemm_bf<1,1>, cudaFuncAttributeMaxDynamicSharedMemorySize, GEMM_SMEM_BYTES);

    embed_kernel<<<MTOK, 256>>>(cs, pe, gt);
    gbias_kernel<<<dim3(512, 64), 256>>>(etm, ee);

    wconv_kernel<<<(786432 + 255)/256, 256>>>(in_w,  786432, 0);
    wconv_kernel<<<(262144 + 255)/256, 256>>>(outw,  262144, 786432);
    wconv_kernel<<<(524288 + 255)/256, 256>>>(ff1w,  524288, 1048576);
    wconv_kernel<<<(524288 + 255)/256, 256>>>(ff2w,  524288, 1572864);

    for (int i = 0; i < LNUM; ++i) {
        const int inoff  = 0       + i*196608;
        const int outoff = 786432  + i*65536;
        const int f1off  = 1048576 + i*131072;
        const int f2off  = 1572864 + i*131072;

        ln_kernel<<<MTOK/8, 256>>>(ln1g + i*DD, ln1b + i*DD);
        gemm_bf<0,1><<<dim3(6, 256), 256, GEMM_SMEM_BYTES>>>(
            pah, pal, pwh + inoff, pwl + inoff, in_b + i*768, (float*)0,
            pqh, pql, 768, 256);
        attn_mma<<<BB*HH, 256, ATT_SMEM>>>();
        gemm_bf<2,0><<<dim3(2, 256), 256, GEMM_SMEM_BYTES>>>(
            pah, pal, pwh + outoff, pwl + outoff, outb + i*256, px,
            (__nv_bfloat16*)0, (__nv_bfloat16*)0, 256, 256);
        ln_kernel<<<MTOK/8, 256>>>(ln2g + i*DD, ln2b + i*DD);
        gemm_bf<1,1><<<dim3(4, 256), 256, GEMM_SMEM_BYTES>>>(
            pah, pal, pwh + f1off, pwl + f1off, ff1b + i*512, (float*)0,
            pfh, pfl, 512, 256);
        gemm_bf<2,0><<<dim3(2, 256), 256, GEMM_SMEM_BYTES>>>(
            pfh, pfl, pwh + f2off, pwl + f2off, ff2b + i*256, px,
            (__nv_bfloat16*)0, (__nv_bfloat16*)0, 256, 512);
    }
    head_kernel<<<BB, 64>>>(fc1w, fc1b, polw, polb, valw, valb, out);
}

// round 14
// speedup vs baseline: 1.6437x; 1.0127x over previous
#include <cuda_runtime.h>
#include <cuda_bf16.h>
#include <math.h>
#include <stdint.h>

#define LNUM 4
#define BB   64
#define NNODE 511
#define SS   512
#define DD   256
#define HH   8
#define HDIM 32
#define DFFN 512
#define MTOK (BB*SS)          /* 32768 */

typedef unsigned long long ull;

/* ------------------------------------------------------------------ */
/* Scratch (device globals; no allocations allowed)                    */
/* ------------------------------------------------------------------ */
__device__ float g_x  [(size_t)MTOK*DD];          /* residual stream  */
__device__ __nv_bfloat16 g_qkv_hi[(size_t)MTOK*3*DD];
__device__ __nv_bfloat16 g_qkv_lo[(size_t)MTOK*3*DD];
__device__ __nv_bfloat16 g_a_hi[(size_t)MTOK*DD]; /* activation hi    */
__device__ __nv_bfloat16 g_a_lo[(size_t)MTOK*DD]; /* activation lo    */
__device__ __nv_bfloat16 g_f_hi[(size_t)MTOK*DFFN];
__device__ __nv_bfloat16 g_f_lo[(size_t)MTOK*DFFN];
#define WTOT 2097152
__device__ __nv_bfloat16 g_w_hi[WTOT];
__device__ __nv_bfloat16 g_w_lo[WTOT];
/* per-head bias table: [b][h][q][k] bf16 (256MB) */
__device__ __nv_bfloat16 g_bias[(size_t)BB*HH*SS*SS];

/* ------------------------------------------------------------------ */
/* helpers                                                             */
/* ------------------------------------------------------------------ */
__device__ __forceinline__ uint32_t smem_u32(const void* p) {
    return (uint32_t)__cvta_generic_to_shared((void*)p);
}
__device__ __forceinline__ void split_bf16(float v, __nv_bfloat16& h, __nv_bfloat16& l) {
    h = __float2bfloat16(v);
    l = __float2bfloat16(v - __bfloat162float(h));
}
__device__ __forceinline__ uint32_t pkbf(__nv_bfloat16 a, __nv_bfloat16 b) {
    __nv_bfloat162 t; t.x = a; t.y = b;
    return *(uint32_t*)&t;
}
__device__ __forceinline__ void cp_async16(uint32_t dst, const void* src) {
    asm volatile("cp.async.cg.shared.global [%0], [%1], 16;" :: "r"(dst), "l"(src));
}
__device__ __forceinline__ void cp_commit() {
    asm volatile("cp.async.commit_group;" ::: "memory");
}
template<int N> __device__ __forceinline__ void cp_wait() {
    asm volatile("cp.async.wait_group %0;" :: "n"(N) : "memory");
}
__device__ __forceinline__ void ldsm4(uint32_t* r, uint32_t a) {
    asm volatile("ldmatrix.sync.aligned.m8n8.x4.shared.b16 {%0,%1,%2,%3}, [%4];"
                 : "=r"(r[0]), "=r"(r[1]), "=r"(r[2]), "=r"(r[3]) : "r"(a));
}
__device__ __forceinline__ void mma_bf16(float* c, const uint32_t* a,
                                         uint32_t b0, uint32_t b1) {
    asm volatile(
        "mma.sync.aligned.m16n8k16.row.col.f32.bf16.bf16.f32 "
        "{%0,%1,%2,%3}, {%4,%5,%6,%7}, {%8,%9}, {%0,%1,%2,%3};"
        : "+f"(c[0]), "+f"(c[1]), "+f"(c[2]), "+f"(c[3])
        : "r"(a[0]), "r"(a[1]), "r"(a[2]), "r"(a[3]), "r"(b0), "r"(b1));
}

/* ------------------------------------------------------------------ */
/* embed + bias table build + weight split                             */
/* ------------------------------------------------------------------ */
__global__ void embed_kernel(const int* __restrict__ cs,
                             const float* __restrict__ patch_emb,
                             const float* __restrict__ game_token) {
    int row = blockIdx.x;
    int d   = threadIdx.x;
    int b = row >> 9, s = row & 511;
    float v;
    if (s == 0) v = game_token[d];
    else        v = patch_emb[cs[b*NNODE + s - 1]*DD + d];
    g_x[(size_t)row*DD + d] = v;
}

/* bias[b][h][q][k] = (q==0||k==0) ? 0 : edge_emb[etm[b][q-1][k-1]][h] */
__global__ void gbias_kernel(const int* __restrict__ etm,
                             const float* __restrict__ ee) {
    int q = blockIdx.x, b = blockIdx.y, t = threadIdx.x;
    int k0 = 2*t, k1 = 2*t + 1;
    int t0 = 3, t1 = 3;
    if (q > 0) {
        const int* er = etm + ((size_t)b*NNODE + (q-1))*NNODE;
        if (k0 > 0) t0 = er[k0 - 1];
        t1 = er[k1 - 1];
    }
#pragma unroll
    for (int h = 0; h < HH; ++h) {
        float b0 = (t0 < 3) ? ee[t0*HH + h] : 0.f;
        float b1 = (t1 < 3) ? ee[t1*HH + h] : 0.f;
        uint32_t pv = pkbf(__float2bfloat16(b0), __float2bfloat16(b1));
        size_t off = (((size_t)(b*HH + h)*SS + q) << 9) + k0;
        *(uint32_t*)(g_bias + off) = pv;
    }
}

__global__ void wconv_kernel(const float* __restrict__ src, int n, int off) {
    int i = blockIdx.x*256 + threadIdx.x;
    if (i >= n) return;
    float x = src[i];
    __nv_bfloat16 h, l; split_bf16(x, h, l);
    g_w_hi[off + i] = h;
    g_w_lo[off + i] = l;
}

/* ------------------------------------------------------------------ */
/* layernorm: g_a_{hi,lo} = split(LN(g_x)*g + b)   (one warp per row)  */
/* ------------------------------------------------------------------ */
__global__ void ln_kernel(const float* __restrict__ gam, const float* __restrict__ bet) {
    int w = threadIdx.x >> 5, lane = threadIdx.x & 31;
    int row = blockIdx.x*8 + w;
    const float* xr = g_x + (size_t)row*DD;
    float4 v0 = *(const float4*)(xr + lane*8);
    float4 v1 = *(const float4*)(xr + lane*8 + 4);
    float s = v0.x+v0.y+v0.z+v0.w + v1.x+v1.y+v1.z+v1.w;
    float q = v0.x*v0.x+v0.y*v0.y+v0.z*v0.z+v0.w*v0.w
            + v1.x*v1.x+v1.y*v1.y+v1.z*v1.z+v1.w*v1.w;
#pragma unroll
    for (int o = 16; o; o >>= 1) {
        s += __shfl_xor_sync(0xffffffffu, s, o);
        q += __shfl_xor_sync(0xffffffffu, q, o);
    }
    float m   = s * (1.f/256.f);
    float var = q * (1.f/256.f) - m*m;
    float rs  = rsqrtf(var + 1e-5f);
    int d = lane*8;
    float4 ga = *(const float4*)(gam + d);
    float4 gb = *(const float4*)(gam + d + 4);
    float4 ba = *(const float4*)(bet + d);
    float4 bb = *(const float4*)(bet + d + 4);
    float o8[8];
    o8[0] = (v0.x-m)*rs*ga.x + ba.x;  o8[1] = (v0.y-m)*rs*ga.y + ba.y;
    o8[2] = (v0.z-m)*rs*ga.z + ba.z;  o8[3] = (v0.w-m)*rs*ga.w + ba.w;
    o8[4] = (v1.x-m)*rs*gb.x + bb.x;  o8[5] = (v1.y-m)*rs*gb.y + bb.y;
    o8[6] = (v1.z-m)*rs*gb.z + bb.z;  o8[7] = (v1.w-m)*rs*gb.w + bb.w;
    __nv_bfloat16* hh = g_a_hi + (size_t)row*DD + d;
    __nv_bfloat16* ll = g_a_lo + (size_t)row*DD + d;
#pragma unroll
    for (int p = 0; p < 4; ++p) {
        __nv_bfloat16 h0, l0, h1, l1;
        split_bf16(o8[2*p],   h0, l0);
        split_bf16(o8[2*p+1], h1, l1);
        *(uint32_t*)(hh + 2*p) = pkbf(h0, h1);
        *(uint32_t*)(ll + 2*p) = pkbf(l0, l1);
    }
}

/* ------------------------------------------------------------------ */
/* bf16 tensor-core GEMM: CTA 128x128, warp 64x32, K-chunk 32,         */
/* cp.async double buffer, swizzled ldmatrix.                          */
/* Inline staging indices (no cid arrays) -> ~111 regs -> 2 CTAs/SM.   */
/* VAR: 0 plain fp32, 1 relu, 2 residual add. WB: bf16 hi/lo output.   */
/* ------------------------------------------------------------------ */
#define GEMM_SMEM_BYTES (2*32768)

template<int VAR, int WB>
__global__ void __launch_bounds__(256, 2)
gemm_bf(const __nv_bfloat16* __restrict__ Ahi, const __nv_bfloat16* __restrict__ Alo,
        const __nv_bfloat16* __restrict__ Whi, const __nv_bfloat16* __restrict__ Wlo,
        const float* __restrict__ bias, float* __restrict__ C,
        __nv_bfloat16* __restrict__ Ohi, __nv_bfloat16* __restrict__ Olo,
        int Nn, int K)
{
    extern __shared__ __align__(16) __nv_bfloat16 smb[];
    const int t    = threadIdx.x;
    const int lane = t & 31;
    const int wid  = t >> 5;
    const int wm   = wid & 1;
    const int wn   = wid >> 1;
    const int m0   = blockIdx.y * 128;
    const int n0   = blockIdx.x * 128;
    const int NC   = K >> 5;
    const uint32_t sb = smem_u32(smb);

    const __nv_bfloat16* mp[4] = {
        Ahi + (size_t)m0*K, Alo + (size_t)m0*K,
        Whi + (size_t)n0*K, Wlo + (size_t)n0*K };

    float acc[4][4][4];
#pragma unroll
    for (int i = 0; i < 4; ++i)
#pragma unroll
        for (int j = 0; j < 4; ++j)
#pragma unroll
            for (int q = 0; q < 4; ++q) acc[i][j][q] = 0.f;

    {
#pragma unroll
        for (int i = 0; i < 8; ++i) {
            int id = i*256 + t;
            int mi = id >> 9;
            int rem = id & 511;
            int r = rem >> 2, cs = rem & 3;
            uint32_t dst = sb + mi*8192 + r*64 + ((cs ^ ((r>>1)&3))<<4);
            cp_async16(dst, mp[mi] + (size_t)r*K + cs*8);
        }
        cp_commit();
    }

    const int lr = lane & 15;
    const int lc = lane >> 4;

    for (int c = 0; c < NC; ++c) {
        if (c + 1 < NC) {
            int kc = (c+1) << 5;
            uint32_t dbase = sb + ((c+1)&1)*32768;
#pragma unroll
            for (int i = 0; i < 8; ++i) {
                int id = i*256 + t;
                int mi = id >> 9;
                int rem = id & 511;
                int r = rem >> 2, cs = rem & 3;
                uint32_t dst = dbase + mi*8192 + r*64 + ((cs ^ ((r>>1)&3))<<4);
                cp_async16(dst, mp[mi] + (size_t)r*K + kc + cs*8);
            }
            cp_commit();
            cp_wait<1>();
        } else {
            cp_wait<0>();
        }
        __syncthreads();

        uint32_t bb = sb + (c&1)*32768;
#pragma unroll
        for (int ks = 0; ks < 2; ++ks) {
            int cseg = ks*2 + lc;
            uint32_t bh[2][4], bl[2][4];
#pragma unroll
            for (int np = 0; np < 2; ++np) {
                int r = wn*32 + np*16 + lr;
                uint32_t off = r*64 + ((cseg ^ ((r>>1)&3))<<4);
                ldsm4(bh[np], bb + 2*8192 + off);
                ldsm4(bl[np], bb + 3*8192 + off);
            }
#pragma unroll
            for (int mt = 0; mt < 4; ++mt) {
                int r = wm*64 + mt*16 + lr;
                uint32_t off = r*64 + ((cseg ^ ((r>>1)&3))<<4);
                uint32_t ah[4], al[4];
                ldsm4(ah, bb + off);
                ldsm4(al, bb + 8192 + off);
#pragma unroll
                for (int nt = 0; nt < 4; ++nt) {
                    int np = nt >> 1, h2 = nt & 1;
                    mma_bf16(acc[mt][nt], ah, bh[np][h2], bh[np][h2+2]);
                    mma_bf16(acc[mt][nt], ah, bl[np][h2], bl[np][h2+2]);
                    mma_bf16(acc[mt][nt], al, bh[np][h2], bh[np][h2+2]);
                }
            }
        }
        __syncthreads();
    }

#pragma unroll
    for (int mt = 0; mt < 4; ++mt) {
#pragma unroll
        for (int nt = 0; nt < 4; ++nt) {
            int r0 = m0 + wm*64 + mt*16 + (lane >> 2);
            int cc = n0 + wn*32 + nt*8 + ((lane & 3) << 1);
            float b0 = bias[cc], b1 = bias[cc + 1];
            float v0 = acc[mt][nt][0] + b0;
            float v1 = acc[mt][nt][1] + b1;
            float v2 = acc[mt][nt][2] + b0;
            float v3 = acc[mt][nt][3] + b1;
            if (VAR == 1) {
                v0 = fmaxf(v0, 0.f); v1 = fmaxf(v1, 0.f);
                v2 = fmaxf(v2, 0.f); v3 = fmaxf(v3, 0.f);
            }
            if (WB) {
                __nv_bfloat16 h0,l0,h1,l1;
                split_bf16(v0, h0, l0); split_bf16(v1, h1, l1);
                *(uint32_t*)(Ohi + (size_t)r0*Nn + cc) = pkbf(h0, h1);
                *(uint32_t*)(Olo + (size_t)r0*Nn + cc) = pkbf(l0, l1);
                split_bf16(v2, h0, l0); split_bf16(v3, h1, l1);
                *(uint32_t*)(Ohi + (size_t)(r0+8)*Nn + cc) = pkbf(h0, h1);
                *(uint32_t*)(Olo + (size_t)(r0+8)*Nn + cc) = pkbf(l0, l1);
            } else {
                float* p0 = C + (size_t)r0*Nn + cc;
                float* p1 = C + (size_t)(r0 + 8)*Nn + cc;
                if (VAR == 2) {
                    float2 o0 = *(float2*)p0, o1 = *(float2*)p1;
                    v0 += o0.x; v1 += o0.y; v2 += o1.x; v3 += o1.y;
                }
                *(float2*)p0 = make_float2(v0, v1);
                *(float2*)p1 = make_float2(v2, v3);
            }
        }
    }
}

/* ------------------------------------------------------------------ */
/* MMA flash attention: one block per (b,h), 256 thr, 64 q-rows/warp.  */
/* QKV arrives pre-split bf16 hi/lo: Q/K staged via cp.async,          */
/* V transposed from bf16 (no cvt). Mainloop = r10 (proven).           */
/* ------------------------------------------------------------------ */
#define AQH 0
#define AQL 32768
#define AKH 65536
#define AKL 98304
#define AVH 131072
#define AVL 163840
#define ATT_SMEM 196608

__global__ void __launch_bounds__(256)
attn_mma() {
    extern __shared__ __align__(16) char smc[];
    const uint32_t sb = smem_u32(smc);
    const int bh = blockIdx.x;
    const int b = bh >> 3, h = bh & 7;
    const int t = threadIdx.x;
    const int w = t >> 5, lane = t & 31;

    const __nv_bfloat16* bhq = g_qkv_hi + ((size_t)b*SS)*768 + h*HDIM;
    const __nv_bfloat16* blq = g_qkv_lo + ((size_t)b*SS)*768 + h*HDIM;

    /* Q/K: pure cp.async into swizzled [row][32] layout (64B rows) */
    for (int i = t; i < 2048; i += 256) {
        int s = i >> 2, seg = i & 3;
        uint32_t qk = s*64 + (((seg) ^ (s&3))<<4);
        const size_t ro = (size_t)s*768 + seg*8;
        cp_async16(sb + AQH + qk, bhq + ro);
        cp_async16(sb + AQL + qk, blq + ro);
        cp_async16(sb + AKH + qk, bhq + ro + 256);
        cp_async16(sb + AKL + qk, blq + ro + 256);
    }
    cp_commit();
    /* V: transpose from bf16 (8 dims per uint4) */
    for (int i = t; i < 2048; i += 256) {
        int s = i >> 2, dg = (i & 3) * 8;
        uint4 vh = *(const uint4*)(bhq + (size_t)s*768 + 512 + dg);
        uint4 vl = *(const uint4*)(blq + (size_t)s*768 + 512 + dg);
        const __nv_bfloat16* ph = (const __nv_bfloat16*)&vh;
        const __nv_bfloat16* pl = (const __nv_bfloat16*)&vl;
        int kseg = s >> 3, sl = (s & 7)*2;
#pragma unroll
        for (int j = 0; j < 8; ++j) {
            int d = dg + j;
            int off = d*1024 + (((kseg) ^ (d&7))<<4) + sl;
            *(__nv_bfloat16*)(smc + AVH + off) = ph[j];
            *(__nv_bfloat16*)(smc + AVL + off) = pl[j];
        }
    }
    cp_wait<0>();
    __syncthreads();

    const int qw = w * 64;
    const int r1 = lane >> 2;
    const int c2 = (lane & 3) << 1;
    const float inv = 0.17677669529663687f;
    const __nv_bfloat16* gb = g_bias + ((size_t)(b*HH + h) << 18);

    float O[4][4][4];
    float mr[4][2], lr[4][2];
#pragma unroll
    for (int mt = 0; mt < 4; ++mt) {
#pragma unroll
        for (int dn = 0; dn < 4; ++dn)
#pragma unroll
            for (int q = 0; q < 4; ++q) O[mt][dn][q] = 0.f;
        mr[mt][0] = -1e30f; mr[mt][1] = -1e30f;
        lr[mt][0] = 0.f;    lr[mt][1] = 0.f;
    }

    const int tile = lane >> 3;

    for (int c = 0; c < 16; ++c) {
        float S[4][4][4];
#pragma unroll
        for (int mt = 0; mt < 4; ++mt)
#pragma unroll
            for (int nt = 0; nt < 4; ++nt)
#pragma unroll
                for (int q = 0; q < 4; ++q) S[mt][nt][q] = 0.f;

        /* ---- QK^T ---- */
#pragma unroll
        for (int ks = 0; ks < 2; ++ks) {
            uint32_t bkh[4][2], bkl[4][2];
#pragma unroll
            for (int np = 0; np < 2; ++np) {
                int nt = np*2 + (tile >> 1);
                int key = c*32 + nt*8 + (lane & 7);
                int seg = ks*2 + (tile & 1);
                uint32_t addr = sb + AKH + key*64 + ((seg ^ (key & 3))<<4);
                uint32_t r4[4];
                ldsm4(r4, addr);
                bkh[np*2][0] = r4[0]; bkh[np*2][1] = r4[1];
                bkh[np*2+1][0] = r4[2]; bkh[np*2+1][1] = r4[3];
                ldsm4(r4, addr + 32768);
                bkl[np*2][0] = r4[0]; bkl[np*2][1] = r4[1];
                bkl[np*2+1][0] = r4[2]; bkl[np*2+1][1] = r4[3];
            }
#pragma unroll
            for (int mt = 0; mt < 4; ++mt) {
                int rr = (tile & 1)*8 + (lane & 7);
                int row = qw + mt*16 + rr;
                int seg = ks*2 + (tile >> 1);
                uint32_t addr = sb + AQH + row*64 + ((seg ^ (row & 3))<<4);
                uint32_t aqh[4], aql[4];
                ldsm4(aqh, addr);
                ldsm4(aql, addr + 32768);
#pragma unroll
                for (int nt = 0; nt < 4; ++nt) {
                    mma_bf16(S[mt][nt], aqh, bkh[nt][0], bkh[nt][1]);
                    mma_bf16(S[mt][nt], aqh, bkl[nt][0], bkl[nt][1]);
                    mma_bf16(S[mt][nt], aql, bkh[nt][0], bkh[nt][1]);
                }
            }
        }

        /* ---- bias + scale + online softmax update ---- */
#pragma unroll
        for (int mt = 0; mt < 4; ++mt) {
#pragma unroll
            for (int h2 = 0; h2 < 2; ++h2) {
                int row = qw + mt*16 + h2*8 + r1;
                const __nv_bfloat16* gr = gb + (((size_t)row) << 9) + c*32 + c2;
                float vmax = -1e30f;
#pragma unroll
                for (int nt = 0; nt < 4; ++nt) {
                    uint32_t bp = *(const uint32_t*)(gr + nt*8);
                    __nv_bfloat162 b2 = *(__nv_bfloat162*)&bp;
                    float v0 = S[mt][nt][h2*2]   * inv + __bfloat162float(b2.x);
                    float v1 = S[mt][nt][h2*2+1] * inv + __bfloat162float(b2.y);
                    S[mt][nt][h2*2] = v0; S[mt][nt][h2*2+1] = v1;
                    vmax = fmaxf(vmax, fmaxf(v0, v1));
                }
                vmax = fmaxf(vmax, __shfl_xor_sync(0xffffffffu, vmax, 1));
                vmax = fmaxf(vmax, __shfl_xor_sync(0xffffffffu, vmax, 2));
                float mo = mr[mt][h2];
                float mn = fmaxf(mo, vmax);
                float alpha = __expf(mo - mn);
                mr[mt][h2] = mn;
                float rs = 0.f;
#pragma unroll
                for (int nt = 0; nt < 4; ++nt) {
                    float p0 = __expf(S[mt][nt][h2*2]   - mn);
                    float p1 = __expf(S[mt][nt][h2*2+1] - mn);
                    S[mt][nt][h2*2] = p0; S[mt][nt][h2*2+1] = p1;
                    rs += p0 + p1;
                }
                rs += __shfl_xor_sync(0xffffffffu, rs, 1);
                rs += __shfl_xor_sync(0xffffffffu, rs, 2);
                lr[mt][h2] = lr[mt][h2]*alpha + rs;
#pragma unroll
                for (int dn = 0; dn < 4; ++dn) {
                    O[mt][dn][h2*2]   *= alpha;
                    O[mt][dn][h2*2+1] *= alpha;
                }
            }
        }

        /* ---- PV ---- */
#pragma unroll
        for (int j = 0; j < 2; ++j) {
            uint32_t bvh[4][2], bvl[4][2];
#pragma unroll
            for (int dp = 0; dp < 2; ++dp) {
                int dn = dp*2 + (tile >> 1);
                int dim = dn*8 + (lane & 7);
                int kseg = c*4 + j*2 + (tile & 1);
                uint32_t addr = sb + AVH + dim*1024 + ((kseg ^ (dim & 7))<<4);
                uint32_t r4[4];
                ldsm4(r4, addr);
                bvh[dp*2][0] = r4[0]; bvh[dp*2][1] = r4[1];
                bvh[dp*2+1][0] = r4[2]; bvh[dp*2+1][1] = r4[3];
                ldsm4(r4, addr + 32768);
                bvl[dp*2][0] = r4[0]; bvl[dp*2][1] = r4[1];
                bvl[dp*2+1][0] = r4[2]; bvl[dp*2+1][1] = r4[3];
            }
#pragma unroll
            for (int mt = 0; mt < 4; ++mt) {
                uint32_t ph[4], pl[4];
                float p00 = S[mt][2*j][0],   p01 = S[mt][2*j][1];
                float p02 = S[mt][2*j][2],   p03 = S[mt][2*j][3];
                float p10 = S[mt][2*j+1][0], p11 = S[mt][2*j+1][1];
                float p12 = S[mt][2*j+1][2], p13 = S[mt][2*j+1][3];
                __nv_bfloat16 h00 = __float2bfloat16(p00), h01 = __float2bfloat16(p01);
                __nv_bfloat16 h02 = __float2bfloat16(p02), h03 = __float2bfloat16(p03);
                __nv_bfloat16 h10 = __float2bfloat16(p10), h11 = __float2bfloat16(p11);
                __nv_bfloat16 h12 = __float2bfloat16(p12), h13 = __float2bfloat16(p13);
                ph[0] = pkbf(h00, h01); ph[1] = pkbf(h02, h03);
                ph[2] = pkbf(h10, h11); ph[3] = pkbf(h12, h13);
                pl[0] = pkbf(__float2bfloat16(p00 - __bfloat162float(h00)),
                             __float2bfloat16(p01 - __bfloat162float(h01)));
                pl[1] = pkbf(__float2bfloat16(p02 - __bfloat162float(h02)),
                             __float2bfloat16(p03 - __bfloat162float(h03)));
                pl[2] = pkbf(__float2bfloat16(p10 - __bfloat162float(h10)),
                             __float2bfloat16(p11 - __bfloat162float(h11)));
                pl[3] = pkbf(__float2bfloat16(p12 - __bfloat162float(h12)),
                             __float2bfloat16(p13 - __bfloat162float(h13)));
#pragma unroll
                for (int dn = 0; dn < 4; ++dn) {
                    mma_bf16(O[mt][dn], ph, bvh[dn][0], bvh[dn][1]);
                    mma_bf16(O[mt][dn], ph, bvl[dn][0], bvl[dn][1]);
                    mma_bf16(O[mt][dn], pl, bvh[dn][0], bvh[dn][1]);
                }
            }
        }
    }

    /* ---- finalize: O /= l, write bf16 hi/lo ---- */
#pragma unroll
    for (int mt = 0; mt < 4; ++mt) {
#pragma unroll
        for (int h2 = 0; h2 < 2; ++h2) {
            float il = 1.f / lr[mt][h2];
            int row = b*SS + qw + mt*16 + h2*8 + r1;
#pragma unroll
            for (int dn = 0; dn < 4; ++dn) {
                float v0 = O[mt][dn][h2*2]   * il;
                float v1 = O[mt][dn][h2*2+1] * il;
                __nv_bfloat16 h0, l0, h1, l1;
                split_bf16(v0, h0, l0);
                split_bf16(v1, h1, l1);
                int col = h*HDIM + dn*8 + c2;
                *(uint32_t*)(g_a_hi + (size_t)row*DD + col) = pkbf(h0, h1);
                *(uint32_t*)(g_a_lo + (size_t)row*DD + col) = pkbf(l0, l1);
            }
        }
    }
}

/* ------------------------------------------------------------------ */
/* head                                                                */
/* ------------------------------------------------------------------ */
__global__ void head_kernel(const float* __restrict__ fc1w, const float* __restrict__ fc1b,
                            const float* __restrict__ polw, const float* __restrict__ polb,
                            const float* __restrict__ valw, const float* __restrict__ valb,
                            float* __restrict__ out) {
    __shared__ float gs[256];
    __shared__ float os[64];
    int b = blockIdx.x, t = threadIdx.x;
    const float* xr = g_x + ((size_t)b*SS)*DD;
#pragma unroll
    for (int i = 0; i < 4; ++i) gs[t + i*64] = xr[t + i*64];
    __syncthreads();
    float a = fc1b[t];
#pragma unroll 8
    for (int k = 0; k < 256; ++k) a += gs[k] * fc1w[t*256 + k];
    os[t] = fmaxf(a, 0.f);
    __syncthreads();
    if (t < 7) {
        float pacc = polb[t];
#pragma unroll
        for (int j = 0; j < 64; ++j) pacc += os[j] * polw[t*64 + j];
        out[b*7 + t] = pacc;
    }
    if (t == 7) {
        float va = valb[0];
#pragma unroll
        for (int j = 0; j < 64; ++j) va += os[j] * valw[j];
        out[BB*7 + b] = tanhf(va);
    }
}

/* ------------------------------------------------------------------ */
extern "C" void kernel_launch(void* const* d_in, const int* in_sizes, int n_in,
                              void* d_out, int out_size) {
    const int*   cs    = (const int*)d_in[0];
    const int*   etm   = (const int*)d_in[1];
    const float* pe    = (const float*)d_in[2];
    const float* gt    = (const float*)d_in[3];
    const float* ee    = (const float*)d_in[4];
    const float* in_w  = (const float*)d_in[5];
    const float* in_b  = (const float*)d_in[6];
    const float* outw  = (const float*)d_in[7];
    const float* outb  = (const float*)d_in[8];
    const float* ff1w  = (const float*)d_in[9];
    const float* ff1b  = (const float*)d_in[10];
    const float* ff2w  = (const float*)d_in[11];
    const float* ff2b  = (const float*)d_in[12];
    const float* ln1g  = (const float*)d_in[13];
    const float* ln1b  = (const float*)d_in[14];
    const float* ln2g  = (const float*)d_in[15];
    const float* ln2b  = (const float*)d_in[16];
    const float* fc1w  = (const float*)d_in[17];
    const float* fc1b  = (const float*)d_in[18];
    const float* polw  = (const float*)d_in[19];
    const float* polb  = (const float*)d_in[20];
    const float* valw  = (const float*)d_in[21];
    const float* valb  = (const float*)d_in[22];
    float* out = (float*)d_out;

    float *px;
    __nv_bfloat16 *pqh, *pql, *pah, *pal, *pfh, *pfl, *pwh, *pwl;
    cudaGetSymbolAddress((void**)&px,  g_x);
    cudaGetSymbolAddress((void**)&pqh, g_qkv_hi);
    cudaGetSymbolAddress((void**)&pql, g_qkv_lo);
    cudaGetSymbolAddress((void**)&pah, g_a_hi);
    cudaGetSymbolAddress((void**)&pal, g_a_lo);
    cudaGetSymbolAddress((void**)&pfh, g_f_hi);
    cudaGetSymbolAddress((void**)&pfl, g_f_lo);
    cudaGetSymbolAddress((void**)&pwh, g_w_hi);
    cudaGetSymbolAddress((void**)&pwl, g_w_lo);

    cudaFuncSetAttribute(attn_mma, cudaFuncAttributeMaxDynamicSharedMemorySize, ATT_SMEM);
    cudaFuncSetAttribute(gemm_bf<0,1>, cudaFuncAttributeMaxDynamicSharedMemorySize, GEMM_SMEM_BYTES);
    cudaFuncSetAttribute(gemm_bf<2,0>, cudaFuncAttributeMaxDynamicSharedMemorySize, GEMM_SMEM_BYTES);
    cudaFuncSetAttribute(gemm_bf<1,1>, cudaFuncAttributeMaxDynamicSharedMemorySize, GEMM_SMEM_BYTES);

    embed_kernel<<<MTOK, 256>>>(cs, pe, gt);
    gbias_kernel<<<dim3(512, 64), 256>>>(etm, ee);

    wconv_kernel<<<(786432 + 255)/256, 256>>>(in_w,  786432, 0);
    wconv_kernel<<<(262144 + 255)/256, 256>>>(outw,  262144, 786432);
    wconv_kernel<<<(524288 + 255)/256, 256>>>(ff1w,  524288, 1048576);
    wconv_kernel<<<(524288 + 255)/256, 256>>>(ff2w,  524288, 1572864);

    for (int i = 0; i < LNUM; ++i) {
        const int inoff  = 0       + i*196608;
        const int outoff = 786432  + i*65536;
        const int f1off  = 1048576 + i*131072;
        const int f2off  = 1572864 + i*131072;

        ln_kernel<<<MTOK/8, 256>>>(ln1g + i*DD, ln1b + i*DD);
        gemm_bf<0,1><<<dim3(6, 256), 256, GEMM_SMEM_BYTES>>>(
            pah, pal, pwh + inoff, pwl + inoff, in_b + i*768, (float*)0,
            pqh, pql, 768, 256);
        attn_mma<<<BB*HH, 256, ATT_SMEM>>>();
        gemm_bf<2,0><<<dim3(2, 256), 256, GEMM_SMEM_BYTES>>>(
            pah, pal, pwh + outoff, pwl + outoff, outb + i*256, px,
            (__nv_bfloat16*)0, (__nv_bfloat16*)0, 256, 256);
        ln_kernel<<<MTOK/8, 256>>>(ln2g + i*DD, ln2b + i*DD);
        gemm_bf<1,1><<<dim3(4, 256), 256, GEMM_SMEM_BYTES>>>(
            pah, pal, pwh + f1off, pwl + f1off, ff1b + i*512, (float*)0,
            pfh, pfl, 512, 256);
        gemm_bf<2,0><<<dim3(2, 256), 256, GEMM_SMEM_BYTES>>>(
            pfh, pfl, pwh + f2off, pwl + f2off, ff2b + i*256, px,
            (__nv_bfloat16*)0, (__nv_bfloat16*)0, 256, 512);
    }
    head_kernel<<<BB, 64>>>(fc1w, fc1b, polw, polb, valw, valb, out);
}

// round 15
// speedup vs baseline: 1.6660x; 1.0135x over previous
#include <cuda_runtime.h>
#include <cuda_bf16.h>
#include <math.h>
#include <stdint.h>

#define LNUM 4
#define BB   64
#define NNODE 511
#define SS   512
#define DD   256
#define HH   8
#define HDIM 32
#define DFFN 512
#define MTOK (BB*SS)          /* 32768 */

typedef unsigned long long ull;

/* ------------------------------------------------------------------ */
/* Scratch (device globals; no allocations allowed)                    */
/* ------------------------------------------------------------------ */
__device__ float g_x  [(size_t)MTOK*DD];          /* residual stream  */
__device__ __nv_bfloat16 g_qkv_hi[(size_t)MTOK*3*DD];
__device__ __nv_bfloat16 g_qkv_lo[(size_t)MTOK*3*DD];
__device__ __nv_bfloat16 g_a_hi[(size_t)MTOK*DD]; /* activation hi    */
__device__ __nv_bfloat16 g_a_lo[(size_t)MTOK*DD]; /* activation lo    */
__device__ __nv_bfloat16 g_f_hi[(size_t)MTOK*DFFN];
__device__ __nv_bfloat16 g_f_lo[(size_t)MTOK*DFFN];
#define WTOT 2097152
__device__ __nv_bfloat16 g_w_hi[WTOT];
__device__ __nv_bfloat16 g_w_lo[WTOT];
/* per-head bias table: [b][h][q][k] bf16 (256MB) */
__device__ __nv_bfloat16 g_bias[(size_t)BB*HH*SS*SS];

/* ------------------------------------------------------------------ */
/* helpers                                                             */
/* ------------------------------------------------------------------ */
__device__ __forceinline__ uint32_t smem_u32(const void* p) {
    return (uint32_t)__cvta_generic_to_shared((void*)p);
}
__device__ __forceinline__ void split_bf16(float v, __nv_bfloat16& h, __nv_bfloat16& l) {
    h = __float2bfloat16(v);
    l = __float2bfloat16(v - __bfloat162float(h));
}
__device__ __forceinline__ uint32_t pkbf(__nv_bfloat16 a, __nv_bfloat16 b) {
    __nv_bfloat162 t; t.x = a; t.y = b;
    return *(uint32_t*)&t;
}
__device__ __forceinline__ void cp_async16(uint32_t dst, const void* src) {
    asm volatile("cp.async.cg.shared.global [%0], [%1], 16;" :: "r"(dst), "l"(src));
}
__device__ __forceinline__ void cp_commit() {
    asm volatile("cp.async.commit_group;" ::: "memory");
}
template<int N> __device__ __forceinline__ void cp_wait() {
    asm volatile("cp.async.wait_group %0;" :: "n"(N) : "memory");
}
__device__ __forceinline__ void ldsm4(uint32_t* r, uint32_t a) {
    asm volatile("ldmatrix.sync.aligned.m8n8.x4.shared.b16 {%0,%1,%2,%3}, [%4];"
                 : "=r"(r[0]), "=r"(r[1]), "=r"(r[2]), "=r"(r[3]) : "r"(a));
}
__device__ __forceinline__ void mma_bf16(float* c, const uint32_t* a,
                                         uint32_t b0, uint32_t b1) {
    asm volatile(
        "mma.sync.aligned.m16n8k16.row.col.f32.bf16.bf16.f32 "
        "{%0,%1,%2,%3}, {%4,%5,%6,%7}, {%8,%9}, {%0,%1,%2,%3};"
        : "+f"(c[0]), "+f"(c[1]), "+f"(c[2]), "+f"(c[3])
        : "r"(a[0]), "r"(a[1]), "r"(a[2]), "r"(a[3]), "r"(b0), "r"(b1));
}

/* ------------------------------------------------------------------ */
/* embed + bias table build + weight split (two-source, merged)        */
/* ------------------------------------------------------------------ */
__global__ void embed_kernel(const int* __restrict__ cs,
                             const float* __restrict__ patch_emb,
                             const float* __restrict__ game_token) {
    int row = blockIdx.x;
    int d   = threadIdx.x;
    int b = row >> 9, s = row & 511;
    float v;
    if (s == 0) v = game_token[d];
    else        v = patch_emb[cs[b*NNODE + s - 1]*DD + d];
    g_x[(size_t)row*DD + d] = v;
}

/* bias[b][h][q][k] = (q==0||k==0) ? 0 : edge_emb[etm[b][q-1][k-1]][h] */
__global__ void gbias_kernel(const int* __restrict__ etm,
                             const float* __restrict__ ee) {
    int q = blockIdx.x, b = blockIdx.y, t = threadIdx.x;
    int k0 = 2*t, k1 = 2*t + 1;
    int t0 = 3, t1 = 3;
    if (q > 0) {
        const int* er = etm + ((size_t)b*NNODE + (q-1))*NNODE;
        if (k0 > 0) t0 = er[k0 - 1];
        t1 = er[k1 - 1];
    }
#pragma unroll
    for (int h = 0; h < HH; ++h) {
        float b0 = (t0 < 3) ? ee[t0*HH + h] : 0.f;
        float b1 = (t1 < 3) ? ee[t1*HH + h] : 0.f;
        uint32_t pv = pkbf(__float2bfloat16(b0), __float2bfloat16(b1));
        size_t off = (((size_t)(b*HH + h)*SS + q) << 9) + k0;
        *(uint32_t*)(g_bias + off) = pv;
    }
}

__global__ void wconv2_kernel(const float* __restrict__ s1, int n1,
                              const float* __restrict__ s2, int n2, int off) {
    int i = blockIdx.x*256 + threadIdx.x;
    if (i >= n1 + n2) return;
    float x = (i < n1) ? s1[i] : s2[i - n1];
    __nv_bfloat16 h, l; split_bf16(x, h, l);
    g_w_hi[off + i] = h;
    g_w_lo[off + i] = l;
}

/* ------------------------------------------------------------------ */
/* layernorm: g_a_{hi,lo} = split(LN(g_x)*g + b)   (one warp per row)  */
/* ------------------------------------------------------------------ */
__global__ void ln_kernel(const float* __restrict__ gam, const float* __restrict__ bet) {
    int w = threadIdx.x >> 5, lane = threadIdx.x & 31;
    int row = blockIdx.x*8 + w;
    const float* xr = g_x + (size_t)row*DD;
    float4 v0 = *(const float4*)(xr + lane*8);
    float4 v1 = *(const float4*)(xr + lane*8 + 4);
    float s = v0.x+v0.y+v0.z+v0.w + v1.x+v1.y+v1.z+v1.w;
    float q = v0.x*v0.x+v0.y*v0.y+v0.z*v0.z+v0.w*v0.w
            + v1.x*v1.x+v1.y*v1.y+v1.z*v1.z+v1.w*v1.w;
#pragma unroll
    for (int o = 16; o; o >>= 1) {
        s += __shfl_xor_sync(0xffffffffu, s, o);
        q += __shfl_xor_sync(0xffffffffu, q, o);
    }
    float m   = s * (1.f/256.f);
    float var = q * (1.f/256.f) - m*m;
    float rs  = rsqrtf(var + 1e-5f);
    int d = lane*8;
    float4 ga = *(const float4*)(gam + d);
    float4 gb = *(const float4*)(gam + d + 4);
    float4 ba = *(const float4*)(bet + d);
    float4 bb = *(const float4*)(bet + d + 4);
    float o8[8];
    o8[0] = (v0.x-m)*rs*ga.x + ba.x;  o8[1] = (v0.y-m)*rs*ga.y + ba.y;
    o8[2] = (v0.z-m)*rs*ga.z + ba.z;  o8[3] = (v0.w-m)*rs*ga.w + ba.w;
    o8[4] = (v1.x-m)*rs*gb.x + bb.x;  o8[5] = (v1.y-m)*rs*gb.y + bb.y;
    o8[6] = (v1.z-m)*rs*gb.z + bb.z;  o8[7] = (v1.w-m)*rs*gb.w + bb.w;
    __nv_bfloat16* hh = g_a_hi + (size_t)row*DD + d;
    __nv_bfloat16* ll = g_a_lo + (size_t)row*DD + d;
#pragma unroll
    for (int p = 0; p < 4; ++p) {
        __nv_bfloat16 h0, l0, h1, l1;
        split_bf16(o8[2*p],   h0, l0);
        split_bf16(o8[2*p+1], h1, l1);
        *(uint32_t*)(hh + 2*p) = pkbf(h0, h1);
        *(uint32_t*)(ll + 2*p) = pkbf(l0, l1);
    }
}

/* ------------------------------------------------------------------ */
/* bf16 tensor-core GEMM: CTA 128x128, warp 64x32, K-chunk 32,         */
/* 3-stage cp.async pipeline (single barrier per chunk), 2 CTAs/SM.    */
/* VAR: 0 plain fp32, 1 relu, 2 residual add. WB: bf16 hi/lo output.   */
/* ------------------------------------------------------------------ */
#define GEMM_SMEM_BYTES (3*32768)

template<int VAR, int WB>
__global__ void __launch_bounds__(256, 2)
gemm_bf(const __nv_bfloat16* __restrict__ Ahi, const __nv_bfloat16* __restrict__ Alo,
        const __nv_bfloat16* __restrict__ Whi, const __nv_bfloat16* __restrict__ Wlo,
        const float* __restrict__ bias, float* __restrict__ C,
        __nv_bfloat16* __restrict__ Ohi, __nv_bfloat16* __restrict__ Olo,
        int Nn, int K)
{
    extern __shared__ __align__(16) __nv_bfloat16 smb[];
    const int t    = threadIdx.x;
    const int lane = t & 31;
    const int wid  = t >> 5;
    const int wm   = wid & 1;
    const int wn   = wid >> 1;
    const int m0   = blockIdx.y * 128;
    const int n0   = blockIdx.x * 128;
    const int NC   = K >> 5;
    const uint32_t sb = smem_u32(smb);

    const __nv_bfloat16* mp[4] = {
        Ahi + (size_t)m0*K, Alo + (size_t)m0*K,
        Whi + (size_t)n0*K, Wlo + (size_t)n0*K };

    float acc[4][4][4];
#pragma unroll
    for (int i = 0; i < 4; ++i)
#pragma unroll
        for (int j = 0; j < 4; ++j)
#pragma unroll
            for (int q = 0; q < 4; ++q) acc[i][j][q] = 0.f;

    /* issue one 32-K chunk into buffer buf */
#define GISSUE(kc, buf)                                                       \
    {                                                                         \
        uint32_t dbase = sb + (buf)*32768;                                    \
        _Pragma("unroll")                                                     \
        for (int i = 0; i < 8; ++i) {                                         \
            int id = i*256 + t;                                               \
            int mi = id >> 9;                                                 \
            int rem = id & 511;                                               \
            int r = rem >> 2, cs2 = rem & 3;                                  \
            uint32_t dst = dbase + mi*8192 + r*64 + ((cs2 ^ ((r>>1)&3))<<4);  \
            cp_async16(dst, mp[mi] + (size_t)r*K + (kc) + cs2*8);             \
        }                                                                     \
        cp_commit();                                                          \
    }

    GISSUE(0, 0);
    GISSUE(32, 1);

    const int lr = lane & 15;
    const int lc = lane >> 4;

    for (int c = 0; c < NC; ++c) {
        if (c == NC - 1) cp_wait<0>(); else cp_wait<1>();
        __syncthreads();

        const int buf = c % 3;
        uint32_t bb = sb + buf*32768;
#pragma unroll
        for (int ks = 0; ks < 2; ++ks) {
            int cseg = ks*2 + lc;
            uint32_t bh[2][4], bl[2][4];
#pragma unroll
            for (int np = 0; np < 2; ++np) {
                int r = wn*32 + np*16 + lr;
                uint32_t off = r*64 + ((cseg ^ ((r>>1)&3))<<4);
                ldsm4(bh[np], bb + 2*8192 + off);
                ldsm4(bl[np], bb + 3*8192 + off);
            }
#pragma unroll
            for (int mt = 0; mt < 4; ++mt) {
                int r = wm*64 + mt*16 + lr;
                uint32_t off = r*64 + ((cseg ^ ((r>>1)&3))<<4);
                uint32_t ah[4], al[4];
                ldsm4(ah, bb + off);
                ldsm4(al, bb + 8192 + off);
#pragma unroll
                for (int nt = 0; nt < 4; ++nt) {
                    int np = nt >> 1, h2 = nt & 1;
                    mma_bf16(acc[mt][nt], ah, bh[np][h2], bh[np][h2+2]);
                    mma_bf16(acc[mt][nt], ah, bl[np][h2], bl[np][h2+2]);
                    mma_bf16(acc[mt][nt], al, bh[np][h2], bh[np][h2+2]);
                }
            }
        }
        if (c + 2 < NC) {
            GISSUE((c+2) << 5, (c+2) % 3);
        }
    }
#undef GISSUE

#pragma unroll
    for (int mt = 0; mt < 4; ++mt) {
#pragma unroll
        for (int nt = 0; nt < 4; ++nt) {
            int r0 = m0 + wm*64 + mt*16 + (lane >> 2);
            int cc = n0 + wn*32 + nt*8 + ((lane & 3) << 1);
            float b0 = bias[cc], b1 = bias[cc + 1];
            float v0 = acc[mt][nt][0] + b0;
            float v1 = acc[mt][nt][1] + b1;
            float v2 = acc[mt][nt][2] + b0;
            float v3 = acc[mt][nt][3] + b1;
            if (VAR == 1) {
                v0 = fmaxf(v0, 0.f); v1 = fmaxf(v1, 0.f);
                v2 = fmaxf(v2, 0.f); v3 = fmaxf(v3, 0.f);
            }
            if (WB) {
                __nv_bfloat16 h0,l0,h1,l1;
                split_bf16(v0, h0, l0); split_bf16(v1, h1, l1);
                *(uint32_t*)(Ohi + (size_t)r0*Nn + cc) = pkbf(h0, h1);
                *(uint32_t*)(Olo + (size_t)r0*Nn + cc) = pkbf(l0, l1);
                split_bf16(v2, h0, l0); split_bf16(v3, h1, l1);
                *(uint32_t*)(Ohi + (size_t)(r0+8)*Nn + cc) = pkbf(h0, h1);
                *(uint32_t*)(Olo + (size_t)(r0+8)*Nn + cc) = pkbf(l0, l1);
            } else {
                float* p0 = C + (size_t)r0*Nn + cc;
                float* p1 = C + (size_t)(r0 + 8)*Nn + cc;
                if (VAR == 2) {
                    float2 o0 = *(float2*)p0, o1 = *(float2*)p1;
                    v0 += o0.x; v1 += o0.y; v2 += o1.x; v3 += o1.y;
                }
                *(float2*)p0 = make_float2(v0, v1);
                *(float2*)p1 = make_float2(v2, v3);
            }
        }
    }
}

/* ------------------------------------------------------------------ */
/* MMA flash attention: one block per (b,h), 256 thr, 64 q-rows/warp.  */
/* QKV arrives pre-split bf16 hi/lo: Q/K staged via cp.async,          */
/* V transposed from bf16 (no cvt). Mainloop = r10 (proven).           */
/* ------------------------------------------------------------------ */
#define AQH 0
#define AQL 32768
#define AKH 65536
#define AKL 98304
#define AVH 131072
#define AVL 163840
#define ATT_SMEM 196608

__global__ void __launch_bounds__(256)
attn_mma() {
    extern __shared__ __align__(16) char smc[];
    const uint32_t sb = smem_u32(smc);
    const int bh = blockIdx.x;
    const int b = bh >> 3, h = bh & 7;
    const int t = threadIdx.x;
    const int w = t >> 5, lane = t & 31;

    const __nv_bfloat16* bhq = g_qkv_hi + ((size_t)b*SS)*768 + h*HDIM;
    const __nv_bfloat16* blq = g_qkv_lo + ((size_t)b*SS)*768 + h*HDIM;

    /* Q/K: pure cp.async into swizzled [row][32] layout (64B rows) */
    for (int i = t; i < 2048; i += 256) {
        int s = i >> 2, seg = i & 3;
        uint32_t qk = s*64 + (((seg) ^ (s&3))<<4);
        const size_t ro = (size_t)s*768 + seg*8;
        cp_async16(sb + AQH + qk, bhq + ro);
        cp_async16(sb + AQL + qk, blq + ro);
        cp_async16(sb + AKH + qk, bhq + ro + 256);
        cp_async16(sb + AKL + qk, blq + ro + 256);
    }
    cp_commit();
    /* V: transpose from bf16 (8 dims per uint4) */
    for (int i = t; i < 2048; i += 256) {
        int s = i >> 2, dg = (i & 3) * 8;
        uint4 vh = *(const uint4*)(bhq + (size_t)s*768 + 512 + dg);
        uint4 vl = *(const uint4*)(blq + (size_t)s*768 + 512 + dg);
        const __nv_bfloat16* ph = (const __nv_bfloat16*)&vh;
        const __nv_bfloat16* pl = (const __nv_bfloat16*)&vl;
        int kseg = s >> 3, sl = (s & 7)*2;
#pragma unroll
        for (int j = 0; j < 8; ++j) {
            int d = dg + j;
            int off = d*1024 + (((kseg) ^ (d&7))<<4) + sl;
            *(__nv_bfloat16*)(smc + AVH + off) = ph[j];
            *(__nv_bfloat16*)(smc + AVL + off) = pl[j];
        }
    }
    cp_wait<0>();
    __syncthreads();

    const int qw = w * 64;
    const int r1 = lane >> 2;
    const int c2 = (lane & 3) << 1;
    const float inv = 0.17677669529663687f;
    const __nv_bfloat16* gb = g_bias + ((size_t)(b*HH + h) << 18);

    float O[4][4][4];
    float mr[4][2], lr[4][2];
#pragma unroll
    for (int mt = 0; mt < 4; ++mt) {
#pragma unroll
        for (int dn = 0; dn < 4; ++dn)
#pragma unroll
            for (int q = 0; q < 4; ++q) O[mt][dn][q] = 0.f;
        mr[mt][0] = -1e30f; mr[mt][1] = -1e30f;
        lr[mt][0] = 0.f;    lr[mt][1] = 0.f;
    }

    const int tile = lane >> 3;

    for (int c = 0; c < 16; ++c) {
        float S[4][4][4];
#pragma unroll
        for (int mt = 0; mt < 4; ++mt)
#pragma unroll
            for (int nt = 0; nt < 4; ++nt)
#pragma unroll
                for (int q = 0; q < 4; ++q) S[mt][nt][q] = 0.f;

        /* ---- QK^T ---- */
#pragma unroll
        for (int ks = 0; ks < 2; ++ks) {
            uint32_t bkh[4][2], bkl[4][2];
#pragma unroll
            for (int np = 0; np < 2; ++np) {
                int nt = np*2 + (tile >> 1);
                int key = c*32 + nt*8 + (lane & 7);
                int seg = ks*2 + (tile & 1);
                uint32_t addr = sb + AKH + key*64 + ((seg ^ (key & 3))<<4);
                uint32_t r4[4];
                ldsm4(r4, addr);
                bkh[np*2][0] = r4[0]; bkh[np*2][1] = r4[1];
                bkh[np*2+1][0] = r4[2]; bkh[np*2+1][1] = r4[3];
                ldsm4(r4, addr + 32768);
                bkl[np*2][0] = r4[0]; bkl[np*2][1] = r4[1];
                bkl[np*2+1][0] = r4[2]; bkl[np*2+1][1] = r4[3];
            }
#pragma unroll
            for (int mt = 0; mt < 4; ++mt) {
                int rr = (tile & 1)*8 + (lane & 7);
                int row = qw + mt*16 + rr;
                int seg = ks*2 + (tile >> 1);
                uint32_t addr = sb + AQH + row*64 + ((seg ^ (row & 3))<<4);
                uint32_t aqh[4], aql[4];
                ldsm4(aqh, addr);
                ldsm4(aql, addr + 32768);
#pragma unroll
                for (int nt = 0; nt < 4; ++nt) {
                    mma_bf16(S[mt][nt], aqh, bkh[nt][0], bkh[nt][1]);
                    mma_bf16(S[mt][nt], aqh, bkl[nt][0], bkl[nt][1]);
                    mma_bf16(S[mt][nt], aql, bkh[nt][0], bkh[nt][1]);
                }
            }
        }

        /* ---- bias + scale + online softmax update ---- */
#pragma unroll
        for (int mt = 0; mt < 4; ++mt) {
#pragma unroll
            for (int h2 = 0; h2 < 2; ++h2) {
                int row = qw + mt*16 + h2*8 + r1;
                const __nv_bfloat16* gr = gb + (((size_t)row) << 9) + c*32 + c2;
                float vmax = -1e30f;
#pragma unroll
                for (int nt = 0; nt < 4; ++nt) {
                    uint32_t bp = *(const uint32_t*)(gr + nt*8);
                    __nv_bfloat162 b2 = *(__nv_bfloat162*)&bp;
                    float v0 = S[mt][nt][h2*2]   * inv + __bfloat162float(b2.x);
                    float v1 = S[mt][nt][h2*2+1] * inv + __bfloat162float(b2.y);
                    S[mt][nt][h2*2] = v0; S[mt][nt][h2*2+1] = v1;
                    vmax = fmaxf(vmax, fmaxf(v0, v1));
                }
                vmax = fmaxf(vmax, __shfl_xor_sync(0xffffffffu, vmax, 1));
                vmax = fmaxf(vmax, __shfl_xor_sync(0xffffffffu, vmax, 2));
                float mo = mr[mt][h2];
                float mn = fmaxf(mo, vmax);
                float alpha = __expf(mo - mn);
                mr[mt][h2] = mn;
                float rs = 0.f;
#pragma unroll
                for (int nt = 0; nt < 4; ++nt) {
                    float p0 = __expf(S[mt][nt][h2*2]   - mn);
                    float p1 = __expf(S[mt][nt][h2*2+1] - mn);
                    S[mt][nt][h2*2] = p0; S[mt][nt][h2*2+1] = p1;
                    rs += p0 + p1;
                }
                rs += __shfl_xor_sync(0xffffffffu, rs, 1);
                rs += __shfl_xor_sync(0xffffffffu, rs, 2);
                lr[mt][h2] = lr[mt][h2]*alpha + rs;
#pragma unroll
                for (int dn = 0; dn < 4; ++dn) {
                    O[mt][dn][h2*2]   *= alpha;
                    O[mt][dn][h2*2+1] *= alpha;
                }
            }
        }

        /* ---- PV ---- */
#pragma unroll
        for (int j = 0; j < 2; ++j) {
            uint32_t bvh[4][2], bvl[4][2];
#pragma unroll
            for (int dp = 0; dp < 2; ++dp) {
                int dn = dp*2 + (tile >> 1);
                int dim = dn*8 + (lane & 7);
                int kseg = c*4 + j*2 + (tile & 1);
                uint32_t addr = sb + AVH + dim*1024 + ((kseg ^ (dim & 7))<<4);
                uint32_t r4[4];
                ldsm4(r4, addr);
                bvh[dp*2][0] = r4[0]; bvh[dp*2][1] = r4[1];
                bvh[dp*2+1][0] = r4[2]; bvh[dp*2+1][1] = r4[3];
                ldsm4(r4, addr + 32768);
                bvl[dp*2][0] = r4[0]; bvl[dp*2][1] = r4[1];
                bvl[dp*2+1][0] = r4[2]; bvl[dp*2+1][1] = r4[3];
            }
#pragma unroll
            for (int mt = 0; mt < 4; ++mt) {
                uint32_t ph[4], pl[4];
                float p00 = S[mt][2*j][0],   p01 = S[mt][2*j][1];
                float p02 = S[mt][2*j][2],   p03 = S[mt][2*j][3];
                float p10 = S[mt][2*j+1][0], p11 = S[mt][2*j+1][1];
                float p12 = S[mt][2*j+1][2], p13 = S[mt][2*j+1][3];
                __nv_bfloat16 h00 = __float2bfloat16(p00), h01 = __float2bfloat16(p01);
                __nv_bfloat16 h02 = __float2bfloat16(p02), h03 = __float2bfloat16(p03);
                __nv_bfloat16 h10 = __float2bfloat16(p10), h11 = __float2bfloat16(p11);
                __nv_bfloat16 h12 = __float2bfloat16(p12), h13 = __float2bfloat16(p13);
                ph[0] = pkbf(h00, h01); ph[1] = pkbf(h02, h03);
                ph[2] = pkbf(h10, h11); ph[3] = pkbf(h12, h13);
                pl[0] = pkbf(__float2bfloat16(p00 - __bfloat162float(h00)),
                             __float2bfloat16(p01 - __bfloat162float(h01)));
                pl[1] = pkbf(__float2bfloat16(p02 - __bfloat162float(h02)),
                             __float2bfloat16(p03 - __bfloat162float(h03)));
                pl[2] = pkbf(__float2bfloat16(p10 - __bfloat162float(h10)),
                             __float2bfloat16(p11 - __bfloat162float(h11)));
                pl[3] = pkbf(__float2bfloat16(p12 - __bfloat162float(h12)),
                             __float2bfloat16(p13 - __bfloat162float(h13)));
#pragma unroll
                for (int dn = 0; dn < 4; ++dn) {
                    mma_bf16(O[mt][dn], ph, bvh[dn][0], bvh[dn][1]);
                    mma_bf16(O[mt][dn], ph, bvl[dn][0], bvl[dn][1]);
                    mma_bf16(O[mt][dn], pl, bvh[dn][0], bvh[dn][1]);
                }
            }
        }
    }

    /* ---- finalize: O /= l, write bf16 hi/lo ---- */
#pragma unroll
    for (int mt = 0; mt < 4; ++mt) {
#pragma unroll
        for (int h2 = 0; h2 < 2; ++h2) {
            float il = 1.f / lr[mt][h2];
            int row = b*SS + qw + mt*16 + h2*8 + r1;
#pragma unroll
            for (int dn = 0; dn < 4; ++dn) {
                float v0 = O[mt][dn][h2*2]   * il;
                float v1 = O[mt][dn][h2*2+1] * il;
                __nv_bfloat16 h0, l0, h1, l1;
                split_bf16(v0, h0, l0);
                split_bf16(v1, h1, l1);
                int col = h*HDIM + dn*8 + c2;
                *(uint32_t*)(g_a_hi + (size_t)row*DD + col) = pkbf(h0, h1);
                *(uint32_t*)(g_a_lo + (size_t)row*DD + col) = pkbf(l0, l1);
            }
        }
    }
}

/* ------------------------------------------------------------------ */
/* head                                                                */
/* ------------------------------------------------------------------ */
__global__ void head_kernel(const float* __restrict__ fc1w, const float* __restrict__ fc1b,
                            const float* __restrict__ polw, const float* __restrict__ polb,
                            const float* __restrict__ valw, const float* __restrict__ valb,
                            float* __restrict__ out) {
    __shared__ float gs[256];
    __shared__ float os[64];
    int b = blockIdx.x, t = threadIdx.x;
    const float* xr = g_x + ((size_t)b*SS)*DD;
#pragma unroll
    for (int i = 0; i < 4; ++i) gs[t + i*64] = xr[t + i*64];
    __syncthreads();
    float a = fc1b[t];
#pragma unroll 8
    for (int k = 0; k < 256; ++k) a += gs[k] * fc1w[t*256 + k];
    os[t] = fmaxf(a, 0.f);
    __syncthreads();
    if (t < 7) {
        float pacc = polb[t];
#pragma unroll
        for (int j = 0; j < 64; ++j) pacc += os[j] * polw[t*64 + j];
        out[b*7 + t] = pacc;
    }
    if (t == 7) {
        float va = valb[0];
#pragma unroll
        for (int j = 0; j < 64; ++j) va += os[j] * valw[j];
        out[BB*7 + b] = tanhf(va);
    }
}

/* ------------------------------------------------------------------ */
extern "C" void kernel_launch(void* const* d_in, const int* in_sizes, int n_in,
                              void* d_out, int out_size) {
    const int*   cs    = (const int*)d_in[0];
    const int*   etm   = (const int*)d_in[1];
    const float* pe    = (const float*)d_in[2];
    const float* gt    = (const float*)d_in[3];
    const float* ee    = (const float*)d_in[4];
    const float* in_w  = (const float*)d_in[5];
    const float* in_b  = (const float*)d_in[6];
    const float* outw  = (const float*)d_in[7];
    const float* outb  = (const float*)d_in[8];
    const float* ff1w  = (const float*)d_in[9];
    const float* ff1b  = (const float*)d_in[10];
    const float* ff2w  = (const float*)d_in[11];
    const float* ff2b  = (const float*)d_in[12];
    const float* ln1g  = (const float*)d_in[13];
    const float* ln1b  = (const float*)d_in[14];
    const float* ln2g  = (const float*)d_in[15];
    const float* ln2b  = (const float*)d_in[16];
    const float* fc1w  = (const float*)d_in[17];
    const float* fc1b  = (const float*)d_in[18];
    const float* polw  = (const float*)d_in[19];
    const float* polb  = (const float*)d_in[20];
    const float* valw  = (const float*)d_in[21];
    const float* valb  = (const float*)d_in[22];
    float* out = (float*)d_out;

    float *px;
    __nv_bfloat16 *pqh, *pql, *pah, *pal, *pfh, *pfl, *pwh, *pwl;
    cudaGetSymbolAddress((void**)&px,  g_x);
    cudaGetSymbolAddress((void**)&pqh, g_qkv_hi);
    cudaGetSymbolAddress((void**)&pql, g_qkv_lo);
    cudaGetSymbolAddress((void**)&pah, g_a_hi);
    cudaGetSymbolAddress((void**)&pal, g_a_lo);
    cudaGetSymbolAddress((void**)&pfh, g_f_hi);
    cudaGetSymbolAddress((void**)&pfl, g_f_lo);
    cudaGetSymbolAddress((void**)&pwh, g_w_hi);
    cudaGetSymbolAddress((void**)&pwl, g_w_lo);

    cudaFuncSetAttribute(attn_mma, cudaFuncAttributeMaxDynamicSharedMemorySize, ATT_SMEM);
    cudaFuncSetAttribute(gemm_bf<0,1>, cudaFuncAttributeMaxDynamicSharedMemorySize, GEMM_SMEM_BYTES);
    cudaFuncSetAttribute(gemm_bf<2,0>, cudaFuncAttributeMaxDynamicSharedMemorySize, GEMM_SMEM_BYTES);
    cudaFuncSetAttribute(gemm_bf<1,1>, cudaFuncAttributeMaxDynamicSharedMemorySize, GEMM_SMEM_BYTES);

    /* launch order arranged so ncu (-s 5 -c 1) captures gemm_bf<0,1> */
    wconv2_kernel<<<(786432 + 262144 + 255)/256, 256>>>(in_w, 786432, outw, 262144, 0);
    wconv2_kernel<<<(524288 + 524288 + 255)/256, 256>>>(ff1w, 524288, ff2w, 524288, 1048576);
    embed_kernel<<<MTOK, 256>>>(cs, pe, gt);
    gbias_kernel<<<dim3(512, 64), 256>>>(etm, ee);

    for (int i = 0; i < LNUM; ++i) {
        const int inoff  = 0       + i*196608;
        const int outoff = 786432  + i*65536;
        const int f1off  = 1048576 + i*131072;
        const int f2off  = 1572864 + i*131072;

        ln_kernel<<<MTOK/8, 256>>>(ln1g + i*DD, ln1b + i*DD);
        gemm_bf<0,1><<<dim3(6, 256), 256, GEMM_SMEM_BYTES>>>(
            pah, pal, pwh + inoff, pwl + inoff, in_b + i*768, (float*)0,
            pqh, pql, 768, 256);
        attn_mma<<<BB*HH, 256, ATT_SMEM>>>();
        gemm_bf<2,0><<<dim3(2, 256), 256, GEMM_SMEM_BYTES>>>(
            pah, pal, pwh + outoff, pwl + outoff, outb + i*256, px,
            (__nv_bfloat16*)0, (__nv_bfloat16*)0, 256, 256);
        ln_kernel<<<MTOK/8, 256>>>(ln2g + i*DD, ln2b + i*DD);
        gemm_bf<1,1><<<dim3(4, 256), 256, GEMM_SMEM_BYTES>>>(
            pah, pal, pwh + f1off, pwl + f1off, ff1b + i*512, (float*)0,
            pfh, pfl, 512, 256);
        gemm_bf<2,0><<<dim3(2, 256), 256, GEMM_SMEM_BYTES>>>(
            pfh, pfl, pwh + f2off, pwl + f2off, ff2b + i*256, px,
            (__nv_bfloat16*)0, (__nv_bfloat16*)0, 256, 512);
    }
    head_kernel<<<BB, 64>>>(fc1w, fc1b, polw, polb, valw, valb, out);
}